// round 1
// baseline (speedup 1.0000x reference)
#include <cuda_runtime.h>
#include <cstdint>
#include <cstddef>

// Problem constants (match reference)
#define NN 100000
#define EE 600000
#define DD 128

// ---------------- scratch (static device arrays; no allocation) ----------------
__device__ float g_Q   [(size_t)NN * DD];
__device__ float g_K   [(size_t)NN * DD];
__device__ float g_V   [(size_t)NN * DD];
__device__ float g_SKIP[(size_t)NN * DD];
__device__ float g_AGG [(size_t)NN * DD];
__device__ float g_H   [(size_t)NN * DD];
__device__ float g_T1  [(size_t)NN * DD];
__device__ float g_F2  [(size_t)NN * DD];
__device__ float g_Ef  [(size_t)EE * DD];
__device__ float g_ex  [(size_t)EE * 8];
__device__ float g_den [(size_t)NN * 8];
__device__ int   g_is64;

// ---------------- packed f32x2 helpers ----------------
__device__ __forceinline__ unsigned long long pack2(float x, float y) {
    unsigned long long r;
    asm("mov.b64 %0, {%1, %2};" : "=l"(r) : "f"(x), "f"(y));
    return r;
}
__device__ __forceinline__ void unpack2(unsigned long long v, float& x, float& y) {
    asm("mov.b64 {%0, %1}, %2;" : "=f"(x), "=f"(y) : "l"(v));
}
__device__ __forceinline__ void fma2(unsigned long long& d, unsigned long long a,
                                     unsigned long long b) {
    asm("fma.rn.f32x2 %0, %1, %2, %0;" : "+l"(d) : "l"(a), "l"(b));
}

// ---------------- edge index dtype detection ----------------
__global__ void detect_idx_kernel(const long long* __restrict__ p, int E, int N) {
    if (threadIdx.x == 0 && blockIdx.x == 0) {
        int ok64 = 1;
        int n = (E < 64) ? E : 64;
        for (int i = 0; i < n; i++) {
            long long v = p[i];
            if (v < 0 || v >= (long long)N) { ok64 = 0; break; }
        }
        g_is64 = ok64;
    }
}

__device__ __forceinline__ int load_idx(const void* p, long long i, int is64) {
    if (is64) return (int)((const long long*)p)[i];
    return ((const int*)p)[i];
}

// ---------------- zero accumulators ----------------
__global__ void zero_kernel(float* __restrict__ a, size_t na,
                            float* __restrict__ b, size_t nb) {
    size_t i = (size_t)blockIdx.x * blockDim.x + threadIdx.x;
    size_t stride = (size_t)gridDim.x * blockDim.x;
    for (size_t j = i; j < na; j += stride) a[j] = 0.0f;
    for (size_t j = i; j < nb; j += stride) b[j] = 0.0f;
}

// ---------------- GEMM: C[M,128] = A[M,128] @ W[128,128] (+bias)(+silu) ----------------
// 256 threads/block, 64 rows/block. Dynamic smem: A tile 32KB + W 64KB = 96KB.
// Each thread: 4 rows x 8 cols micro-tile using packed fma.rn.f32x2.
__global__ void gemm128_kernel(const float* __restrict__ A, const float* __restrict__ W,
                               const float* __restrict__ bias, float* __restrict__ C,
                               int M, int act) {
    extern __shared__ float sm[];
    float* As = sm;               // [64][128]
    float* Ws = sm + 64 * 128;    // [128][128]

    int tid  = threadIdx.x;
    int row0 = blockIdx.x * 64;

    // stage W (4096 float4)
    {
        const float4* Wg = (const float4*)W;
        float4* Wsv = (float4*)Ws;
#pragma unroll
        for (int i = 0; i < 16; i++) Wsv[tid + i * 256] = Wg[tid + i * 256];
    }
    // stage A tile (2048 float4), zero-pad out-of-range rows
    {
        float4* Asv = (float4*)As;
#pragma unroll
        for (int i = 0; i < 8; i++) {
            int idx = tid + i * 256;
            int r = idx >> 5;
            int c = idx & 31;
            float4 v = make_float4(0.f, 0.f, 0.f, 0.f);
            if (row0 + r < M)
                v = ((const float4*)(A + (size_t)(row0 + r) * DD))[c];
            Asv[idx] = v;
        }
    }
    __syncthreads();

    int rg = tid >> 4;   // 0..15 -> rows rg*4 .. rg*4+3
    int cg = tid & 15;   // 0..15 -> cols cg*8 .. cg*8+7

    unsigned long long acc[4][4];
#pragma unroll
    for (int i = 0; i < 4; i++)
#pragma unroll
        for (int j = 0; j < 4; j++) acc[i][j] = 0ull;  // (0.f,0.f)

#pragma unroll 8
    for (int k = 0; k < 128; k++) {
        unsigned long long av[4];
#pragma unroll
        for (int i = 0; i < 4; i++) {
            float a = As[(rg * 4 + i) * 128 + k];
            av[i] = pack2(a, a);
        }
        const ulonglong2* wp = (const ulonglong2*)Ws + ((size_t)k * 32 + cg * 2);
        ulonglong2 wa = wp[0];  // cols c..c+3
        ulonglong2 wb = wp[1];  // cols c+4..c+7
#pragma unroll
        for (int i = 0; i < 4; i++) {
            fma2(acc[i][0], av[i], wa.x);
            fma2(acc[i][1], av[i], wa.y);
            fma2(acc[i][2], av[i], wb.x);
            fma2(acc[i][3], av[i], wb.y);
        }
    }

    // epilogue
    float bv[8];
    if (bias) {
        float4 b0 = ((const float4*)(bias + cg * 8))[0];
        float4 b1 = ((const float4*)(bias + cg * 8))[1];
        bv[0] = b0.x; bv[1] = b0.y; bv[2] = b0.z; bv[3] = b0.w;
        bv[4] = b1.x; bv[5] = b1.y; bv[6] = b1.z; bv[7] = b1.w;
    } else {
#pragma unroll
        for (int c = 0; c < 8; c++) bv[c] = 0.f;
    }

#pragma unroll
    for (int i = 0; i < 4; i++) {
        int r = row0 + rg * 4 + i;
        if (r >= M) continue;
        float o[8];
#pragma unroll
        for (int j = 0; j < 4; j++) unpack2(acc[i][j], o[2 * j], o[2 * j + 1]);
#pragma unroll
        for (int c = 0; c < 8; c++) {
            o[c] += bv[c];
            if (act == 1) o[c] = o[c] / (1.0f + expf(-o[c]));  // SiLU
        }
        float4* out = (float4*)(C + (size_t)r * DD + cg * 8);
        out[0] = make_float4(o[0], o[1], o[2], o[3]);
        out[1] = make_float4(o[4], o[5], o[6], o[7]);
    }
}

// ---------------- attention logits + exp + denominator ----------------
// one warp per edge; lane handles floats [lane*4, lane*4+4); head = lane/4
__global__ void alpha_kernel(const float* __restrict__ Q, const float* __restrict__ K,
                             const float* __restrict__ Ef, const void* __restrict__ eidx,
                             int E, float* __restrict__ exbuf, float* __restrict__ denom) {
    long long gw = ((long long)blockIdx.x * blockDim.x + threadIdx.x) >> 5;
    int lane = threadIdx.x & 31;
    if (gw >= E) return;
    int is64 = g_is64;
    int src = load_idx(eidx, gw, is64);
    int dst = load_idx(eidx, (long long)E + gw, is64);

    float4 q = *(const float4*)&Q[(size_t)dst * DD + lane * 4];
    float4 k = *(const float4*)&K[(size_t)src * DD + lane * 4];
    float4 e = *(const float4*)&Ef[(size_t)gw * DD + lane * 4];

    float p = q.x * (k.x + e.x) + q.y * (k.y + e.y) +
              q.z * (k.z + e.z) + q.w * (k.w + e.w);
    p += __shfl_xor_sync(0xffffffffu, p, 1);
    p += __shfl_xor_sync(0xffffffffu, p, 2);   // 4-lane group = one head (C=16)

    if ((lane & 3) == 0) {
        int h = lane >> 2;
        float ex = expf(p * 0.25f);            // 1/sqrt(C)=0.25; no max-sub (safe range)
        exbuf[(size_t)gw * 8 + h] = ex;
        atomicAdd(&denom[(size_t)dst * 8 + h], ex);
    }
}

// ---------------- normalized message scatter ----------------
__global__ void msg_kernel(const float* __restrict__ V, const float* __restrict__ Ef,
                           const void* __restrict__ eidx, int E,
                           const float* __restrict__ exbuf, const float* __restrict__ denom,
                           float* __restrict__ AGG) {
    long long gw = ((long long)blockIdx.x * blockDim.x + threadIdx.x) >> 5;
    int lane = threadIdx.x & 31;
    if (gw >= E) return;
    int is64 = g_is64;
    int src = load_idx(eidx, gw, is64);
    int dst = load_idx(eidx, (long long)E + gw, is64);
    int h = lane >> 2;

    float ex  = exbuf[(size_t)gw * 8 + h];
    float den = denom[(size_t)dst * 8 + h];
    float w = ex / (den + 1e-16f);

    float4 v = *(const float4*)&V[(size_t)src * DD + lane * 4];
    float4 e = *(const float4*)&Ef[(size_t)gw * DD + lane * 4];

    float* o = &AGG[(size_t)dst * DD + lane * 4];
    atomicAdd(o + 0, w * (v.x + e.x));
    atomicAdd(o + 1, w * (v.y + e.y));
    atomicAdd(o + 2, w * (v.z + e.z));
    atomicAdd(o + 3, w * (v.w + e.w));
}

// ---------------- residual + LayerNorm (one warp per row) ----------------
// out = base + LN(acc1 (+ acc2)) * g + b
__global__ void postln_kernel(const float* __restrict__ base, const float* __restrict__ acc1,
                              const float* __restrict__ acc2, const float* __restrict__ g,
                              const float* __restrict__ b, float* __restrict__ outp, int M) {
    long long gw = ((long long)blockIdx.x * blockDim.x + threadIdx.x) >> 5;
    int lane = threadIdx.x & 31;
    if (gw >= M) return;

    float4 o = *(const float4*)&acc1[(size_t)gw * DD + lane * 4];
    if (acc2) {
        float4 s = *(const float4*)&acc2[(size_t)gw * DD + lane * 4];
        o.x += s.x; o.y += s.y; o.z += s.z; o.w += s.w;
    }
    float sum = o.x + o.y + o.z + o.w;
#pragma unroll
    for (int off = 16; off >= 1; off >>= 1) sum += __shfl_xor_sync(0xffffffffu, sum, off);
    float mu = sum * (1.0f / 128.0f);

    float dx = o.x - mu, dy = o.y - mu, dz = o.z - mu, dw = o.w - mu;
    float ss = dx * dx + dy * dy + dz * dz + dw * dw;
#pragma unroll
    for (int off = 16; off >= 1; off >>= 1) ss += __shfl_xor_sync(0xffffffffu, ss, off);
    float rs = rsqrtf(ss * (1.0f / 128.0f) + 1e-5f);

    float4 gg = *(const float4*)&g[lane * 4];
    float4 bb = *(const float4*)&b[lane * 4];
    float4 xx = *(const float4*)&base[(size_t)gw * DD + lane * 4];

    float4 r;
    r.x = xx.x + dx * rs * gg.x + bb.x;
    r.y = xx.y + dy * rs * gg.y + bb.y;
    r.z = xx.z + dz * rs * gg.z + bb.z;
    r.w = xx.w + dw * rs * gg.w + bb.w;
    *(float4*)&outp[(size_t)gw * DD + lane * 4] = r;
}

// ---------------- launch ----------------
extern "C" void kernel_launch(void* const* d_in, const int* in_sizes, int n_in,
                              void* d_out, int out_size) {
    const void*  eidx      = d_in[0];
    const float* x         = (const float*)d_in[1];
    const float* edge_attr = (const float*)d_in[2];
    const float* Wq = (const float*)d_in[3],  *bq = (const float*)d_in[4];
    const float* Wk = (const float*)d_in[5],  *bk = (const float*)d_in[6];
    const float* Wv = (const float*)d_in[7],  *bv = (const float*)d_in[8];
    const float* We = (const float*)d_in[9];
    const float* Wskip = (const float*)d_in[10], *bskip = (const float*)d_in[11];
    const float* W1 = (const float*)d_in[12], *b1 = (const float*)d_in[13];
    const float* W2 = (const float*)d_in[14], *b2 = (const float*)d_in[15];
    const float* g1 = (const float*)d_in[16], *be1 = (const float*)d_in[17];
    const float* g2 = (const float*)d_in[18], *be2 = (const float*)d_in[19];
    float* out = (float*)d_out;

    int N = in_sizes[1] / DD;   // 100000
    int E = in_sizes[2] / DD;   // 600000

    float *pQ, *pK, *pV, *pSK, *pAGG, *pH, *pT1, *pF2, *pEf, *pEx, *pDen;
    cudaGetSymbolAddress((void**)&pQ,   g_Q);
    cudaGetSymbolAddress((void**)&pK,   g_K);
    cudaGetSymbolAddress((void**)&pV,   g_V);
    cudaGetSymbolAddress((void**)&pSK,  g_SKIP);
    cudaGetSymbolAddress((void**)&pAGG, g_AGG);
    cudaGetSymbolAddress((void**)&pH,   g_H);
    cudaGetSymbolAddress((void**)&pT1,  g_T1);
    cudaGetSymbolAddress((void**)&pF2,  g_F2);
    cudaGetSymbolAddress((void**)&pEf,  g_Ef);
    cudaGetSymbolAddress((void**)&pEx,  g_ex);
    cudaGetSymbolAddress((void**)&pDen, g_den);

    cudaFuncSetAttribute(gemm128_kernel, cudaFuncAttributeMaxDynamicSharedMemorySize,
                         96 * 1024);

    // 1. detect edge_index dtype
    detect_idx_kernel<<<1, 32>>>((const long long*)eidx, E, N);

    // 2. zero accumulators (denom + AGG)
    zero_kernel<<<1024, 256>>>(pDen, (size_t)N * 8, pAGG, (size_t)N * DD);

    // 3. node/edge linear projections
    int nb_node = (N + 63) / 64;
    int nb_edge = (E + 63) / 64;
    size_t smem = 96 * 1024;
    gemm128_kernel<<<nb_node, 256, smem>>>(x, Wq, bq, pQ, N, 0);
    gemm128_kernel<<<nb_node, 256, smem>>>(x, Wk, bk, pK, N, 0);
    gemm128_kernel<<<nb_node, 256, smem>>>(x, Wv, bv, pV, N, 0);
    gemm128_kernel<<<nb_node, 256, smem>>>(x, Wskip, bskip, pSK, N, 0);
    gemm128_kernel<<<nb_edge, 256, smem>>>(edge_attr, We, nullptr, pEf, E, 0);

    // 4. attention: logits -> exp -> denom, then normalized scatter
    int eb = (E + 7) / 8;  // 8 warps/block of 256
    alpha_kernel<<<eb, 256>>>(pQ, pK, pEf, eidx, E, pEx, pDen);
    msg_kernel<<<eb, 256>>>(pV, pEf, eidx, E, pEx, pDen, pAGG);

    // 5. h = x + LN(AGG + skip)
    int nbw = (N + 7) / 8;
    postln_kernel<<<nbw, 256>>>(x, pAGG, pSK, g1, be1, pH, N);

    // 6. FFN
    gemm128_kernel<<<nb_node, 256, smem>>>(pH, W1, b1, pT1, N, 1);   // SiLU
    gemm128_kernel<<<nb_node, 256, smem>>>(pT1, W2, b2, pF2, N, 0);

    // 7. out = h + LN(ffn)
    postln_kernel<<<nbw, 256>>>(pH, pF2, nullptr, g2, be2, out, N);
}

// round 3
// speedup vs baseline: 1.6969x; 1.6969x over previous
#include <cuda_runtime.h>
#include <cstdint>
#include <cstddef>

// Problem constants
#define NN 100000
#define EE 600000
#define DD 128

// ---------------- scratch (static device arrays; no allocation) ----------------
__device__ float g_Q   [(size_t)NN * DD];
__device__ float g_K   [(size_t)NN * DD];
__device__ float g_V   [(size_t)NN * DD];
__device__ float g_SKIP[(size_t)NN * DD];
__device__ float g_AGG [(size_t)NN * DD];
__device__ float g_H   [(size_t)NN * DD];
__device__ float g_T1  [(size_t)NN * DD];
__device__ float g_F2  [(size_t)NN * DD];
__device__ float g_Ef  [(size_t)EE * DD];
__device__ float g_ex  [(size_t)EE * 8];
__device__ float g_den [(size_t)NN * 8];
__device__ int   g_is64;

// ---------------- tf32 helpers ----------------
__device__ __forceinline__ uint32_t f2tf32(float v) {
    uint32_t r;
    asm("cvt.rna.tf32.f32 %0, %1;" : "=r"(r) : "f"(v));
    return r;
}
__device__ __forceinline__ void mma_tf32(float& d0, float& d1, float& d2, float& d3,
                                         uint32_t a0, uint32_t a1, uint32_t a2, uint32_t a3,
                                         uint32_t b0, uint32_t b1) {
    asm volatile(
        "mma.sync.aligned.m16n8k8.row.col.f32.tf32.tf32.f32 "
        "{%0,%1,%2,%3}, {%4,%5,%6,%7}, {%8,%9}, {%0,%1,%2,%3};"
        : "+f"(d0), "+f"(d1), "+f"(d2), "+f"(d3)
        : "r"(a0), "r"(a1), "r"(a2), "r"(a3), "r"(b0), "r"(b1));
}

// smem element strides (floats) — chosen for conflict-free fragment LDS
#define AS_STRIDE 132
#define WS_STRIDE 136
#define AS_ELEMS  (128 * AS_STRIDE)          // 16896
#define WS_ELEMS  (128 * WS_STRIDE)          // 17408
#define SMEM_BYTES ((AS_ELEMS + WS_ELEMS) * 4)  // 137216

// ---------------- tensor-core TF32 GEMM ----------------
// C_i[M,128] = A[M,128] @ W_i[128,128] (+bias_i)(+silu), up to 4 W's sharing staged A.
// 256 threads; CTA tile 128x128; warp tile 32x64 (4 row-groups x 2 col-groups).
__global__ void __launch_bounds__(256, 1)
mma_gemm_kernel(const float* __restrict__ A, int M, int nw, int act,
                const float* Wg0, const float* Wg1, const float* Wg2, const float* Wg3,
                const float* bg0, const float* bg1, const float* bg2, const float* bg3,
                float* og0, float* og1, float* og2, float* og3) {
    extern __shared__ uint32_t sm[];
    uint32_t* As = sm;               // [128][AS_STRIDE] tf32 bits
    uint32_t* Ws = sm + AS_ELEMS;    // [128][WS_STRIDE] tf32 bits

    int tid = threadIdx.x;
    int wid = tid >> 5;
    int lane = tid & 31;
    int row0 = blockIdx.x * 128;

    const float* Wp[4] = {Wg0, Wg1, Wg2, Wg3};
    const float* Bp[4] = {bg0, bg1, bg2, bg3};
    float*       Op[4] = {og0, og1, og2, og3};

    // ---- stage A tile (zero-pad tail rows), convert to tf32 ----
#pragma unroll
    for (int it = 0; it < 16; it++) {
        int idx = it * 256 + tid;
        int r = idx >> 5, c4 = idx & 31;
        float4 v = make_float4(0.f, 0.f, 0.f, 0.f);
        if (row0 + r < M) v = ((const float4*)(A + (size_t)(row0 + r) * DD))[c4];
        uint4 t = make_uint4(f2tf32(v.x), f2tf32(v.y), f2tf32(v.z), f2tf32(v.w));
        *(uint4*)&As[r * AS_STRIDE + c4 * 4] = t;
    }

    int wr = wid & 3;        // row group: rows wr*32 .. +32
    int wc = wid >> 2;       // col group: cols wc*64 .. +64
    int qid = lane >> 2;     // 0..7
    int qln = lane & 3;      // 0..3

    for (int w = 0; w < nw; w++) {
        __syncthreads();
        // ---- stage W_w as [k][n], tf32 ----
        const float* Wgp = Wp[w];
#pragma unroll
        for (int it = 0; it < 16; it++) {
            int idx = it * 256 + tid;
            int k = idx >> 5, c4 = idx & 31;
            float4 v = ((const float4*)(Wgp + (size_t)k * DD))[c4];
            uint4 t = make_uint4(f2tf32(v.x), f2tf32(v.y), f2tf32(v.z), f2tf32(v.w));
            *(uint4*)&Ws[k * WS_STRIDE + c4 * 4] = t;
        }
        __syncthreads();

        // ---- compute: 2 m-tiles x 8 n-tiles of m16n8k8, k-loop 16 steps ----
        float acc[2][8][4];
#pragma unroll
        for (int mt = 0; mt < 2; mt++)
#pragma unroll
            for (int nt = 0; nt < 8; nt++)
#pragma unroll
                for (int j = 0; j < 4; j++) acc[mt][nt][j] = 0.f;

#pragma unroll
        for (int ks = 0; ks < 16; ks++) {
            int k0 = ks * 8;
            uint32_t af[2][4];
#pragma unroll
            for (int mt = 0; mt < 2; mt++) {
                int r = wr * 32 + mt * 16 + qid;
                const uint32_t* ap = &As[r * AS_STRIDE + k0 + qln];
                af[mt][0] = ap[0];
                af[mt][2] = ap[4];
                af[mt][1] = ap[8 * AS_STRIDE];
                af[mt][3] = ap[8 * AS_STRIDE + 4];
            }
#pragma unroll
            for (int nt = 0; nt < 8; nt++) {
                int n0 = wc * 64 + nt * 8;
                uint32_t b0 = Ws[(k0 + qln) * WS_STRIDE + n0 + qid];
                uint32_t b1 = Ws[(k0 + 4 + qln) * WS_STRIDE + n0 + qid];
#pragma unroll
                for (int mt = 0; mt < 2; mt++)
                    mma_tf32(acc[mt][nt][0], acc[mt][nt][1], acc[mt][nt][2], acc[mt][nt][3],
                             af[mt][0], af[mt][1], af[mt][2], af[mt][3], b0, b1);
            }
        }

        // ---- epilogue: bias + optional SiLU, direct global stores ----
        const float* bias = Bp[w];
        float* outp = Op[w];
#pragma unroll
        for (int nt = 0; nt < 8; nt++) {
            int col = wc * 64 + nt * 8 + qln * 2;
            float b0v = 0.f, b1v = 0.f;
            if (bias) { b0v = bias[col]; b1v = bias[col + 1]; }
#pragma unroll
            for (int mt = 0; mt < 2; mt++) {
                int r = row0 + wr * 32 + mt * 16 + qid;
                float o0 = acc[mt][nt][0] + b0v;
                float o1 = acc[mt][nt][1] + b1v;
                float o2 = acc[mt][nt][2] + b0v;
                float o3 = acc[mt][nt][3] + b1v;
                if (act) {
                    o0 = o0 / (1.f + expf(-o0));
                    o1 = o1 / (1.f + expf(-o1));
                    o2 = o2 / (1.f + expf(-o2));
                    o3 = o3 / (1.f + expf(-o3));
                }
                if (r < M)
                    *(float2*)&outp[(size_t)r * DD + col] = make_float2(o0, o1);
                if (r + 8 < M)
                    *(float2*)&outp[(size_t)(r + 8) * DD + col] = make_float2(o2, o3);
            }
        }
    }
}

// ---------------- edge index dtype detection ----------------
__global__ void detect_idx_kernel(const long long* __restrict__ p, int E, int N) {
    if (threadIdx.x == 0 && blockIdx.x == 0) {
        int ok64 = 1;
        int n = (E < 64) ? E : 64;
        for (int i = 0; i < n; i++) {
            long long v = p[i];
            if (v < 0 || v >= (long long)N) { ok64 = 0; break; }
        }
        g_is64 = ok64;
    }
}
__device__ __forceinline__ int load_idx(const void* p, long long i, int is64) {
    if (is64) return (int)((const long long*)p)[i];
    return ((const int*)p)[i];
}

// ---------------- zero accumulators ----------------
__global__ void zero_kernel(float* __restrict__ a, size_t na,
                            float* __restrict__ b, size_t nb) {
    size_t i = (size_t)blockIdx.x * blockDim.x + threadIdx.x;
    size_t stride = (size_t)gridDim.x * blockDim.x;
    for (size_t j = i; j < na; j += stride) a[j] = 0.0f;
    for (size_t j = i; j < nb; j += stride) b[j] = 0.0f;
}

// ---------------- attention logits + exp + denominator ----------------
__global__ void alpha_kernel(const float* __restrict__ Q, const float* __restrict__ K,
                             const float* __restrict__ Ef, const void* __restrict__ eidx,
                             int E, float* __restrict__ exbuf, float* __restrict__ denom) {
    long long gw = ((long long)blockIdx.x * blockDim.x + threadIdx.x) >> 5;
    int lane = threadIdx.x & 31;
    if (gw >= E) return;
    int is64 = g_is64;
    int src = load_idx(eidx, gw, is64);
    int dst = load_idx(eidx, (long long)E + gw, is64);

    float4 q = *(const float4*)&Q[(size_t)dst * DD + lane * 4];
    float4 k = *(const float4*)&K[(size_t)src * DD + lane * 4];
    float4 e = *(const float4*)&Ef[(size_t)gw * DD + lane * 4];

    float p = q.x * (k.x + e.x) + q.y * (k.y + e.y) +
              q.z * (k.z + e.z) + q.w * (k.w + e.w);
    p += __shfl_xor_sync(0xffffffffu, p, 1);
    p += __shfl_xor_sync(0xffffffffu, p, 2);   // 4 lanes = one head (C=16)

    if ((lane & 3) == 0) {
        int h = lane >> 2;
        float ex = expf(p * 0.25f);
        exbuf[(size_t)gw * 8 + h] = ex;
        atomicAdd(&denom[(size_t)dst * 8 + h], ex);
    }
}

// ---------------- normalized message scatter ----------------
__global__ void msg_kernel(const float* __restrict__ V, const float* __restrict__ Ef,
                           const void* __restrict__ eidx, int E,
                           const float* __restrict__ exbuf, const float* __restrict__ denom,
                           float* __restrict__ AGG) {
    long long gw = ((long long)blockIdx.x * blockDim.x + threadIdx.x) >> 5;
    int lane = threadIdx.x & 31;
    if (gw >= E) return;
    int is64 = g_is64;
    int src = load_idx(eidx, gw, is64);
    int dst = load_idx(eidx, (long long)E + gw, is64);
    int h = lane >> 2;

    float ex  = exbuf[(size_t)gw * 8 + h];
    float den = denom[(size_t)dst * 8 + h];
    float w = ex / (den + 1e-16f);

    float4 v = *(const float4*)&V[(size_t)src * DD + lane * 4];
    float4 e = *(const float4*)&Ef[(size_t)gw * DD + lane * 4];

    float* o = &AGG[(size_t)dst * DD + lane * 4];
    atomicAdd(o + 0, w * (v.x + e.x));
    atomicAdd(o + 1, w * (v.y + e.y));
    atomicAdd(o + 2, w * (v.z + e.z));
    atomicAdd(o + 3, w * (v.w + e.w));
}

// ---------------- residual + LayerNorm (one warp per row) ----------------
__global__ void postln_kernel(const float* __restrict__ base, const float* __restrict__ acc1,
                              const float* __restrict__ acc2, const float* __restrict__ g,
                              const float* __restrict__ b, float* __restrict__ outp, int M) {
    long long gw = ((long long)blockIdx.x * blockDim.x + threadIdx.x) >> 5;
    int lane = threadIdx.x & 31;
    if (gw >= M) return;

    float4 o = *(const float4*)&acc1[(size_t)gw * DD + lane * 4];
    if (acc2) {
        float4 s = *(const float4*)&acc2[(size_t)gw * DD + lane * 4];
        o.x += s.x; o.y += s.y; o.z += s.z; o.w += s.w;
    }
    float sum = o.x + o.y + o.z + o.w;
#pragma unroll
    for (int off = 16; off >= 1; off >>= 1) sum += __shfl_xor_sync(0xffffffffu, sum, off);
    float mu = sum * (1.0f / 128.0f);

    float dx = o.x - mu, dy = o.y - mu, dz = o.z - mu, dw = o.w - mu;
    float ss = dx * dx + dy * dy + dz * dz + dw * dw;
#pragma unroll
    for (int off = 16; off >= 1; off >>= 1) ss += __shfl_xor_sync(0xffffffffu, ss, off);
    float rs = rsqrtf(ss * (1.0f / 128.0f) + 1e-5f);

    float4 gg = *(const float4*)&g[lane * 4];
    float4 bb = *(const float4*)&b[lane * 4];
    float4 xx = *(const float4*)&base[(size_t)gw * DD + lane * 4];

    float4 r;
    r.x = xx.x + dx * rs * gg.x + bb.x;
    r.y = xx.y + dy * rs * gg.y + bb.y;
    r.z = xx.z + dz * rs * gg.z + bb.z;
    r.w = xx.w + dw * rs * gg.w + bb.w;
    *(float4*)&outp[(size_t)gw * DD + lane * 4] = r;
}

// ---------------- launch ----------------
extern "C" void kernel_launch(void* const* d_in, const int* in_sizes, int n_in,
                              void* d_out, int out_size) {
    const void*  eidx      = d_in[0];
    const float* x         = (const float*)d_in[1];
    const float* edge_attr = (const float*)d_in[2];
    const float* Wq = (const float*)d_in[3],  *bq = (const float*)d_in[4];
    const float* Wk = (const float*)d_in[5],  *bk = (const float*)d_in[6];
    const float* Wv = (const float*)d_in[7],  *bv = (const float*)d_in[8];
    const float* We = (const float*)d_in[9];
    const float* Wskip = (const float*)d_in[10], *bskip = (const float*)d_in[11];
    const float* W1 = (const float*)d_in[12], *b1 = (const float*)d_in[13];
    const float* W2 = (const float*)d_in[14], *b2 = (const float*)d_in[15];
    const float* g1 = (const float*)d_in[16], *be1 = (const float*)d_in[17];
    const float* g2 = (const float*)d_in[18], *be2 = (const float*)d_in[19];
    float* out = (float*)d_out;

    int N = in_sizes[1] / DD;   // 100000
    int E = in_sizes[2] / DD;   // 600000

    float *pQ, *pK, *pV, *pSK, *pAGG, *pH, *pT1, *pF2, *pEf, *pEx, *pDen;
    cudaGetSymbolAddress((void**)&pQ,   g_Q);
    cudaGetSymbolAddress((void**)&pK,   g_K);
    cudaGetSymbolAddress((void**)&pV,   g_V);
    cudaGetSymbolAddress((void**)&pSK,  g_SKIP);
    cudaGetSymbolAddress((void**)&pAGG, g_AGG);
    cudaGetSymbolAddress((void**)&pH,   g_H);
    cudaGetSymbolAddress((void**)&pT1,  g_T1);
    cudaGetSymbolAddress((void**)&pF2,  g_F2);
    cudaGetSymbolAddress((void**)&pEf,  g_Ef);
    cudaGetSymbolAddress((void**)&pEx,  g_ex);
    cudaGetSymbolAddress((void**)&pDen, g_den);

    cudaFuncSetAttribute(mma_gemm_kernel, cudaFuncAttributeMaxDynamicSharedMemorySize,
                         SMEM_BYTES);

    // 1. detect edge_index dtype
    detect_idx_kernel<<<1, 32>>>((const long long*)eidx, E, N);

    // 2. zero accumulators
    zero_kernel<<<1024, 256>>>(pDen, (size_t)N * 8, pAGG, (size_t)N * DD);

    // 3. projections (tensor-core tf32 mma.sync)
    int nb_node = (N + 127) / 128;
    int nb_edge = (E + 127) / 128;
    mma_gemm_kernel<<<nb_node, 256, SMEM_BYTES>>>(x, N, 4, 0,
        Wq, Wk, Wv, Wskip, bq, bk, bv, bskip, pQ, pK, pV, pSK);
    mma_gemm_kernel<<<nb_edge, 256, SMEM_BYTES>>>(edge_attr, E, 1, 0,
        We, nullptr, nullptr, nullptr, nullptr, nullptr, nullptr, nullptr,
        pEf, nullptr, nullptr, nullptr);

    // 4. attention
    int eb = (E + 7) / 8;
    alpha_kernel<<<eb, 256>>>(pQ, pK, pEf, eidx, E, pEx, pDen);
    msg_kernel<<<eb, 256>>>(pV, pEf, eidx, E, pEx, pDen, pAGG);

    // 5. h = x + LN(AGG + skip)
    int nbw = (N + 7) / 8;
    postln_kernel<<<nbw, 256>>>(x, pAGG, pSK, g1, be1, pH, N);

    // 6. FFN
    mma_gemm_kernel<<<nb_node, 256, SMEM_BYTES>>>(pH, N, 1, 1,
        W1, nullptr, nullptr, nullptr, b1, nullptr, nullptr, nullptr,
        pT1, nullptr, nullptr, nullptr);
    mma_gemm_kernel<<<nb_node, 256, SMEM_BYTES>>>(pT1, N, 1, 0,
        W2, nullptr, nullptr, nullptr, b2, nullptr, nullptr, nullptr,
        pF2, nullptr, nullptr, nullptr);

    // 7. out = h + LN(ffn)
    postln_kernel<<<nbw, 256>>>(pH, pF2, nullptr, g2, be2, out, N);
}

// round 4
// speedup vs baseline: 2.0781x; 1.2246x over previous
#include <cuda_runtime.h>
#include <cstdint>
#include <cstddef>

// Problem constants
#define NN 100000
#define EE 600000
#define DD 128

// ---------------- scratch (static device arrays; no allocation) ----------------
__device__ float g_Q   [(size_t)NN * DD];
__device__ float g_K   [(size_t)NN * DD];
__device__ float g_V   [(size_t)NN * DD];
__device__ float g_SKIP[(size_t)NN * DD];
__device__ float g_AGG [(size_t)NN * DD];
__device__ float g_H   [(size_t)NN * DD];
__device__ float g_T1  [(size_t)NN * DD];
__device__ float g_F2  [(size_t)NN * DD];
__device__ float g_Ef  [(size_t)EE * DD];
__device__ float g_den [(size_t)NN * 8];
__device__ int   g_is64;

// ---------------- tf32 helpers ----------------
__device__ __forceinline__ uint32_t f2tf32(float v) {
    uint32_t r;
    asm("cvt.rna.tf32.f32 %0, %1;" : "=r"(r) : "f"(v));
    return r;
}
__device__ __forceinline__ void mma_tf32(float& d0, float& d1, float& d2, float& d3,
                                         uint32_t a0, uint32_t a1, uint32_t a2, uint32_t a3,
                                         uint32_t b0, uint32_t b1) {
    asm volatile(
        "mma.sync.aligned.m16n8k8.row.col.f32.tf32.tf32.f32 "
        "{%0,%1,%2,%3}, {%4,%5,%6,%7}, {%8,%9}, {%0,%1,%2,%3};"
        : "+f"(d0), "+f"(d1), "+f"(d2), "+f"(d3)
        : "r"(a0), "r"(a1), "r"(a2), "r"(a3), "r"(b0), "r"(b1));
}

// smem strides (floats) — conflict-free fragment LDS
#define AS_STRIDE 132
#define WS_STRIDE 136
#define AS_ELEMS  (64 * AS_STRIDE)                 // 8448  (64-row A tile)
#define WS_ELEMS  (128 * WS_STRIDE)                // 17408
#define SMEM_BYTES ((AS_ELEMS + WS_ELEMS) * 4)     // 103424 -> 2 CTAs/SM

// ---------------- tensor-core TF32 GEMM ----------------
// C_i[M,128] = A[M,128] @ W_i[128,128] (+bias_i)(+silu), up to 4 W's sharing staged A.
// 256 threads; CTA tile 64x128; warp tile 32x32 (2 row-groups x 4 col-groups).
__global__ void __launch_bounds__(256, 2)
mma_gemm_kernel(const float* __restrict__ A, int M, int nw, int act,
                const float* Wg0, const float* Wg1, const float* Wg2, const float* Wg3,
                const float* bg0, const float* bg1, const float* bg2, const float* bg3,
                float* og0, float* og1, float* og2, float* og3) {
    extern __shared__ uint32_t sm[];
    uint32_t* As = sm;               // [64][AS_STRIDE] tf32 bits
    uint32_t* Ws = sm + AS_ELEMS;    // [128][WS_STRIDE] tf32 bits

    int tid = threadIdx.x;
    int wid = tid >> 5;
    int lane = tid & 31;
    int row0 = blockIdx.x * 64;

    const float* Wp[4] = {Wg0, Wg1, Wg2, Wg3};
    const float* Bp[4] = {bg0, bg1, bg2, bg3};
    float*       Op[4] = {og0, og1, og2, og3};

    // ---- stage A tile (64 rows, zero-pad tail), convert to tf32 ----
#pragma unroll
    for (int it = 0; it < 8; it++) {
        int idx = it * 256 + tid;
        int r = idx >> 5, c4 = idx & 31;
        float4 v = make_float4(0.f, 0.f, 0.f, 0.f);
        if (row0 + r < M) v = ((const float4*)(A + (size_t)(row0 + r) * DD))[c4];
        uint4 t = make_uint4(f2tf32(v.x), f2tf32(v.y), f2tf32(v.z), f2tf32(v.w));
        *(uint4*)&As[r * AS_STRIDE + c4 * 4] = t;
    }

    int wr = wid & 1;        // row group: rows wr*32 .. +32
    int wc = wid >> 1;       // col group: cols wc*32 .. +32
    int qid = lane >> 2;     // 0..7
    int qln = lane & 3;      // 0..3

    for (int w = 0; w < nw; w++) {
        __syncthreads();
        // ---- stage W_w as [k][n], tf32 ----
        const float* Wgp = Wp[w];
#pragma unroll
        for (int it = 0; it < 16; it++) {
            int idx = it * 256 + tid;
            int k = idx >> 5, c4 = idx & 31;
            float4 v = ((const float4*)(Wgp + (size_t)k * DD))[c4];
            uint4 t = make_uint4(f2tf32(v.x), f2tf32(v.y), f2tf32(v.z), f2tf32(v.w));
            *(uint4*)&Ws[k * WS_STRIDE + c4 * 4] = t;
        }
        __syncthreads();

        // ---- compute: 2 m-tiles x 4 n-tiles of m16n8k8, k-loop 16 steps ----
        float acc[2][4][4];
#pragma unroll
        for (int mt = 0; mt < 2; mt++)
#pragma unroll
            for (int nt = 0; nt < 4; nt++)
#pragma unroll
                for (int j = 0; j < 4; j++) acc[mt][nt][j] = 0.f;

#pragma unroll
        for (int ks = 0; ks < 16; ks++) {
            int k0 = ks * 8;
            uint32_t af[2][4];
#pragma unroll
            for (int mt = 0; mt < 2; mt++) {
                int r = wr * 32 + mt * 16 + qid;
                const uint32_t* ap = &As[r * AS_STRIDE + k0 + qln];
                af[mt][0] = ap[0];
                af[mt][2] = ap[4];
                af[mt][1] = ap[8 * AS_STRIDE];
                af[mt][3] = ap[8 * AS_STRIDE + 4];
            }
#pragma unroll
            for (int nt = 0; nt < 4; nt++) {
                int n0 = wc * 32 + nt * 8;
                uint32_t b0 = Ws[(k0 + qln) * WS_STRIDE + n0 + qid];
                uint32_t b1 = Ws[(k0 + 4 + qln) * WS_STRIDE + n0 + qid];
#pragma unroll
                for (int mt = 0; mt < 2; mt++)
                    mma_tf32(acc[mt][nt][0], acc[mt][nt][1], acc[mt][nt][2], acc[mt][nt][3],
                             af[mt][0], af[mt][1], af[mt][2], af[mt][3], b0, b1);
            }
        }

        // ---- epilogue: bias + optional SiLU, direct global stores ----
        const float* bias = Bp[w];
        float* outp = Op[w];
#pragma unroll
        for (int nt = 0; nt < 4; nt++) {
            int col = wc * 32 + nt * 8 + qln * 2;
            float b0v = 0.f, b1v = 0.f;
            if (bias) { b0v = bias[col]; b1v = bias[col + 1]; }
#pragma unroll
            for (int mt = 0; mt < 2; mt++) {
                int r = row0 + wr * 32 + mt * 16 + qid;
                float o0 = acc[mt][nt][0] + b0v;
                float o1 = acc[mt][nt][1] + b1v;
                float o2 = acc[mt][nt][2] + b0v;
                float o3 = acc[mt][nt][3] + b1v;
                if (act) {
                    o0 = o0 / (1.f + expf(-o0));
                    o1 = o1 / (1.f + expf(-o1));
                    o2 = o2 / (1.f + expf(-o2));
                    o3 = o3 / (1.f + expf(-o3));
                }
                if (r < M)
                    *(float2*)&outp[(size_t)r * DD + col] = make_float2(o0, o1);
                if (r + 8 < M)
                    *(float2*)&outp[(size_t)(r + 8) * DD + col] = make_float2(o2, o3);
            }
        }
    }
}

// ---------------- edge index dtype detection ----------------
__global__ void detect_idx_kernel(const long long* __restrict__ p, int E, int N) {
    if (threadIdx.x == 0 && blockIdx.x == 0) {
        int ok64 = 1;
        int n = (E < 64) ? E : 64;
        for (int i = 0; i < n; i++) {
            long long v = p[i];
            if (v < 0 || v >= (long long)N) { ok64 = 0; break; }
        }
        g_is64 = ok64;
    }
}
__device__ __forceinline__ int load_idx(const void* p, long long i, int is64) {
    if (is64) return (int)((const long long*)p)[i];
    return ((const int*)p)[i];
}

// ---------------- zero accumulators ----------------
__global__ void zero_kernel(float* __restrict__ a, size_t na,
                            float* __restrict__ b, size_t nb) {
    size_t i = (size_t)blockIdx.x * blockDim.x + threadIdx.x;
    size_t stride = (size_t)gridDim.x * blockDim.x;
    for (size_t j = i; j < na; j += stride) a[j] = 0.0f;
    for (size_t j = i; j < nb; j += stride) b[j] = 0.0f;
}

// ---------------- fused attention: logits + exp + UNNORMALIZED scatter ----------------
// One warp per edge. Accumulates AGG[dst] += ex*(v[src]+e) and den[dst][h] += ex.
// Normalization (divide by den) happens in postln1_kernel — algebraically identical
// to normalizing per-edge.
__global__ void attn_kernel(const float* __restrict__ Q, const float* __restrict__ K,
                            const float* __restrict__ V, const float* __restrict__ Ef,
                            const void* __restrict__ eidx, int E,
                            float* __restrict__ denom, float* __restrict__ AGG) {
    long long gw = ((long long)blockIdx.x * blockDim.x + threadIdx.x) >> 5;
    int lane = threadIdx.x & 31;
    if (gw >= E) return;
    int is64 = g_is64;
    int src = load_idx(eidx, gw, is64);
    int dst = load_idx(eidx, (long long)E + gw, is64);

    float4 q = *(const float4*)&Q[(size_t)dst * DD + lane * 4];
    float4 k = *(const float4*)&K[(size_t)src * DD + lane * 4];
    float4 e = *(const float4*)&Ef[(size_t)gw * DD + lane * 4];

    float p = q.x * (k.x + e.x) + q.y * (k.y + e.y) +
              q.z * (k.z + e.z) + q.w * (k.w + e.w);
    p += __shfl_xor_sync(0xffffffffu, p, 1);
    p += __shfl_xor_sync(0xffffffffu, p, 2);   // 4 lanes = one head (C=16)

    float ex = expf(p * 0.25f);                // 1/sqrt(16); safe range, no max-sub
    if ((lane & 3) == 0)
        atomicAdd(&denom[(size_t)dst * 8 + (lane >> 2)], ex);

    float4 v = *(const float4*)&V[(size_t)src * DD + lane * 4];
    float m0 = ex * (v.x + e.x);
    float m1 = ex * (v.y + e.y);
    float m2 = ex * (v.z + e.z);
    float m3 = ex * (v.w + e.w);

    float* o = &AGG[(size_t)dst * DD + lane * 4];
    asm volatile("red.global.add.v4.f32 [%0], {%1,%2,%3,%4};"
                 :: "l"(o), "f"(m0), "f"(m1), "f"(m2), "f"(m3) : "memory");
}

// ---------------- h = x + LN(AGG/den + SKIP) ----------------
__global__ void postln1_kernel(const float* __restrict__ x, const float* __restrict__ AGG,
                               const float* __restrict__ SKIP, const float* __restrict__ den,
                               const float* __restrict__ g, const float* __restrict__ b,
                               float* __restrict__ outp, int M) {
    long long gw = ((long long)blockIdx.x * blockDim.x + threadIdx.x) >> 5;
    int lane = threadIdx.x & 31;
    if (gw >= M) return;

    float dh = den[(size_t)gw * 8 + (lane >> 2)];
    float inv = 1.0f / (dh + 1e-16f);

    float4 o = *(const float4*)&AGG[(size_t)gw * DD + lane * 4];
    float4 s = *(const float4*)&SKIP[(size_t)gw * DD + lane * 4];
    o.x = o.x * inv + s.x;
    o.y = o.y * inv + s.y;
    o.z = o.z * inv + s.z;
    o.w = o.w * inv + s.w;

    float sum = o.x + o.y + o.z + o.w;
#pragma unroll
    for (int off = 16; off >= 1; off >>= 1) sum += __shfl_xor_sync(0xffffffffu, sum, off);
    float mu = sum * (1.0f / 128.0f);

    float dx = o.x - mu, dy = o.y - mu, dz = o.z - mu, dw = o.w - mu;
    float ss = dx * dx + dy * dy + dz * dz + dw * dw;
#pragma unroll
    for (int off = 16; off >= 1; off >>= 1) ss += __shfl_xor_sync(0xffffffffu, ss, off);
    float rs = rsqrtf(ss * (1.0f / 128.0f) + 1e-5f);

    float4 gg = *(const float4*)&g[lane * 4];
    float4 bb = *(const float4*)&b[lane * 4];
    float4 xx = *(const float4*)&x[(size_t)gw * DD + lane * 4];

    float4 r;
    r.x = xx.x + dx * rs * gg.x + bb.x;
    r.y = xx.y + dy * rs * gg.y + bb.y;
    r.z = xx.z + dz * rs * gg.z + bb.z;
    r.w = xx.w + dw * rs * gg.w + bb.w;
    *(float4*)&outp[(size_t)gw * DD + lane * 4] = r;
}

// ---------------- out = base + LN(acc) ----------------
__global__ void postln2_kernel(const float* __restrict__ base, const float* __restrict__ acc1,
                               const float* __restrict__ g, const float* __restrict__ b,
                               float* __restrict__ outp, int M) {
    long long gw = ((long long)blockIdx.x * blockDim.x + threadIdx.x) >> 5;
    int lane = threadIdx.x & 31;
    if (gw >= M) return;

    float4 o = *(const float4*)&acc1[(size_t)gw * DD + lane * 4];
    float sum = o.x + o.y + o.z + o.w;
#pragma unroll
    for (int off = 16; off >= 1; off >>= 1) sum += __shfl_xor_sync(0xffffffffu, sum, off);
    float mu = sum * (1.0f / 128.0f);

    float dx = o.x - mu, dy = o.y - mu, dz = o.z - mu, dw = o.w - mu;
    float ss = dx * dx + dy * dy + dz * dz + dw * dw;
#pragma unroll
    for (int off = 16; off >= 1; off >>= 1) ss += __shfl_xor_sync(0xffffffffu, ss, off);
    float rs = rsqrtf(ss * (1.0f / 128.0f) + 1e-5f);

    float4 gg = *(const float4*)&g[lane * 4];
    float4 bb = *(const float4*)&b[lane * 4];
    float4 xx = *(const float4*)&base[(size_t)gw * DD + lane * 4];

    float4 r;
    r.x = xx.x + dx * rs * gg.x + bb.x;
    r.y = xx.y + dy * rs * gg.y + bb.y;
    r.z = xx.z + dz * rs * gg.z + bb.z;
    r.w = xx.w + dw * rs * gg.w + bb.w;
    *(float4*)&outp[(size_t)gw * DD + lane * 4] = r;
}

// ---------------- launch ----------------
extern "C" void kernel_launch(void* const* d_in, const int* in_sizes, int n_in,
                              void* d_out, int out_size) {
    const void*  eidx      = d_in[0];
    const float* x         = (const float*)d_in[1];
    const float* edge_attr = (const float*)d_in[2];
    const float* Wq = (const float*)d_in[3],  *bq = (const float*)d_in[4];
    const float* Wk = (const float*)d_in[5],  *bk = (const float*)d_in[6];
    const float* Wv = (const float*)d_in[7],  *bv = (const float*)d_in[8];
    const float* We = (const float*)d_in[9];
    const float* Wskip = (const float*)d_in[10], *bskip = (const float*)d_in[11];
    const float* W1 = (const float*)d_in[12], *b1 = (const float*)d_in[13];
    const float* W2 = (const float*)d_in[14], *b2 = (const float*)d_in[15];
    const float* g1 = (const float*)d_in[16], *be1 = (const float*)d_in[17];
    const float* g2 = (const float*)d_in[18], *be2 = (const float*)d_in[19];
    float* out = (float*)d_out;

    int N = in_sizes[1] / DD;   // 100000
    int E = in_sizes[2] / DD;   // 600000

    float *pQ, *pK, *pV, *pSK, *pAGG, *pH, *pT1, *pF2, *pEf, *pDen;
    cudaGetSymbolAddress((void**)&pQ,   g_Q);
    cudaGetSymbolAddress((void**)&pK,   g_K);
    cudaGetSymbolAddress((void**)&pV,   g_V);
    cudaGetSymbolAddress((void**)&pSK,  g_SKIP);
    cudaGetSymbolAddress((void**)&pAGG, g_AGG);
    cudaGetSymbolAddress((void**)&pH,   g_H);
    cudaGetSymbolAddress((void**)&pT1,  g_T1);
    cudaGetSymbolAddress((void**)&pF2,  g_F2);
    cudaGetSymbolAddress((void**)&pEf,  g_Ef);
    cudaGetSymbolAddress((void**)&pDen, g_den);

    cudaFuncSetAttribute(mma_gemm_kernel, cudaFuncAttributeMaxDynamicSharedMemorySize,
                         SMEM_BYTES);

    // 1. detect edge_index dtype
    detect_idx_kernel<<<1, 32>>>((const long long*)eidx, E, N);

    // 2. zero accumulators
    zero_kernel<<<1024, 256>>>(pDen, (size_t)N * 8, pAGG, (size_t)N * DD);

    // 3. projections (tensor-core tf32 mma.sync)
    int nb_node = (N + 63) / 64;
    int nb_edge = (E + 63) / 64;
    mma_gemm_kernel<<<nb_node, 256, SMEM_BYTES>>>(x, N, 4, 0,
        Wq, Wk, Wv, Wskip, bq, bk, bv, bskip, pQ, pK, pV, pSK);
    mma_gemm_kernel<<<nb_edge, 256, SMEM_BYTES>>>(edge_attr, E, 1, 0,
        We, nullptr, nullptr, nullptr, nullptr, nullptr, nullptr, nullptr,
        pEf, nullptr, nullptr, nullptr);

    // 4. fused attention (single edge pass, unnormalized aggregation)
    int eb = (E + 7) / 8;
    attn_kernel<<<eb, 256>>>(pQ, pK, pV, pEf, eidx, E, pDen, pAGG);

    // 5. h = x + LN(AGG/den + skip)
    int nbw = (N + 7) / 8;
    postln1_kernel<<<nbw, 256>>>(x, pAGG, pSK, pDen, g1, be1, pH, N);

    // 6. FFN
    mma_gemm_kernel<<<nb_node, 256, SMEM_BYTES>>>(pH, N, 1, 1,
        W1, nullptr, nullptr, nullptr, b1, nullptr, nullptr, nullptr,
        pT1, nullptr, nullptr, nullptr);
    mma_gemm_kernel<<<nb_node, 256, SMEM_BYTES>>>(pT1, N, 1, 0,
        W2, nullptr, nullptr, nullptr, b2, nullptr, nullptr, nullptr,
        pF2, nullptr, nullptr, nullptr);

    // 7. out = h + LN(ffn)
    postln2_kernel<<<nbw, 256>>>(pH, pF2, g2, be2, out, N);
}

// round 5
// speedup vs baseline: 2.1757x; 1.0470x over previous
#include <cuda_runtime.h>
#include <cstdint>
#include <cstddef>

// Problem constants
#define NN 100000
#define EE 600000
#define DD 128

// ---------------- scratch (static device arrays; no allocation) ----------------
__device__ float g_Q   [(size_t)NN * DD];
__device__ float g_K   [(size_t)NN * DD];
__device__ float g_V   [(size_t)NN * DD];
__device__ float g_SKIP[(size_t)NN * DD];
__device__ float g_AGG [(size_t)NN * DD];
__device__ float g_H   [(size_t)NN * DD];
__device__ float g_T1  [(size_t)NN * DD];
__device__ float g_F2  [(size_t)NN * DD];
__device__ float g_den [(size_t)NN * 8];
__device__ int   g_is64;

// ---------------- tf32 helpers ----------------
__device__ __forceinline__ uint32_t f2tf32(float v) {
    uint32_t r;
    asm("cvt.rna.tf32.f32 %0, %1;" : "=r"(r) : "f"(v));
    return r;
}
__device__ __forceinline__ void mma_tf32(float& d0, float& d1, float& d2, float& d3,
                                         uint32_t a0, uint32_t a1, uint32_t a2, uint32_t a3,
                                         uint32_t b0, uint32_t b1) {
    asm volatile(
        "mma.sync.aligned.m16n8k8.row.col.f32.tf32.tf32.f32 "
        "{%0,%1,%2,%3}, {%4,%5,%6,%7}, {%8,%9}, {%0,%1,%2,%3};"
        : "+f"(d0), "+f"(d1), "+f"(d2), "+f"(d3)
        : "r"(a0), "r"(a1), "r"(a2), "r"(a3), "r"(b0), "r"(b1));
}

// smem strides (floats) — conflict-free fragment LDS
#define AS_STRIDE 132
#define WS_STRIDE 136
#define AS_ELEMS  (64 * AS_STRIDE)                 // 8448
#define WS_ELEMS  (128 * WS_STRIDE)                // 17408
#define GEMM_SMEM ((AS_ELEMS + WS_ELEMS) * 4)      // 103424 -> 2 CTAs/SM
#define FUSED_SMEM (GEMM_SMEM + 64 * 2 * 4)        // + src/dst index arrays

#define TPC 8   // edge tiles per CTA in fused kernel

__device__ __forceinline__ int load_idx(const void* p, long long i, int is64) {
    if (is64) return (int)((const long long*)p)[i];
    return ((const int*)p)[i];
}

// ---------------- tensor-core TF32 GEMM (node projections / FFN) ----------------
// C_i[M,128] = A[M,128] @ W_i[128,128] (+bias_i)(+silu), up to 4 W's sharing staged A.
// 256 threads; CTA tile 64x128; warp tile 32x32.
__global__ void __launch_bounds__(256, 2)
mma_gemm_kernel(const float* __restrict__ A, int M, int nw, int act,
                const float* Wg0, const float* Wg1, const float* Wg2, const float* Wg3,
                const float* bg0, const float* bg1, const float* bg2, const float* bg3,
                float* og0, float* og1, float* og2, float* og3) {
    extern __shared__ uint32_t sm[];
    uint32_t* As = sm;               // [64][AS_STRIDE]
    uint32_t* Ws = sm + AS_ELEMS;    // [128][WS_STRIDE]

    int tid = threadIdx.x;
    int wid = tid >> 5;
    int lane = tid & 31;
    int row0 = blockIdx.x * 64;

    const float* Wp[4] = {Wg0, Wg1, Wg2, Wg3};
    const float* Bp[4] = {bg0, bg1, bg2, bg3};
    float*       Op[4] = {og0, og1, og2, og3};

#pragma unroll
    for (int it = 0; it < 8; it++) {
        int idx = it * 256 + tid;
        int r = idx >> 5, c4 = idx & 31;
        float4 v = make_float4(0.f, 0.f, 0.f, 0.f);
        if (row0 + r < M) v = ((const float4*)(A + (size_t)(row0 + r) * DD))[c4];
        uint4 t = make_uint4(f2tf32(v.x), f2tf32(v.y), f2tf32(v.z), f2tf32(v.w));
        *(uint4*)&As[r * AS_STRIDE + c4 * 4] = t;
    }

    int wr = wid & 1;
    int wc = wid >> 1;
    int qid = lane >> 2;
    int qln = lane & 3;

    for (int w = 0; w < nw; w++) {
        __syncthreads();
        const float* Wgp = Wp[w];
#pragma unroll
        for (int it = 0; it < 16; it++) {
            int idx = it * 256 + tid;
            int k = idx >> 5, c4 = idx & 31;
            float4 v = ((const float4*)(Wgp + (size_t)k * DD))[c4];
            uint4 t = make_uint4(f2tf32(v.x), f2tf32(v.y), f2tf32(v.z), f2tf32(v.w));
            *(uint4*)&Ws[k * WS_STRIDE + c4 * 4] = t;
        }
        __syncthreads();

        float acc[2][4][4];
#pragma unroll
        for (int mt = 0; mt < 2; mt++)
#pragma unroll
            for (int nt = 0; nt < 4; nt++)
#pragma unroll
                for (int j = 0; j < 4; j++) acc[mt][nt][j] = 0.f;

#pragma unroll
        for (int ks = 0; ks < 16; ks++) {
            int k0 = ks * 8;
            uint32_t af[2][4];
#pragma unroll
            for (int mt = 0; mt < 2; mt++) {
                int r = wr * 32 + mt * 16 + qid;
                const uint32_t* ap = &As[r * AS_STRIDE + k0 + qln];
                af[mt][0] = ap[0];
                af[mt][2] = ap[4];
                af[mt][1] = ap[8 * AS_STRIDE];
                af[mt][3] = ap[8 * AS_STRIDE + 4];
            }
#pragma unroll
            for (int nt = 0; nt < 4; nt++) {
                int n0 = wc * 32 + nt * 8;
                uint32_t b0 = Ws[(k0 + qln) * WS_STRIDE + n0 + qid];
                uint32_t b1 = Ws[(k0 + 4 + qln) * WS_STRIDE + n0 + qid];
#pragma unroll
                for (int mt = 0; mt < 2; mt++)
                    mma_tf32(acc[mt][nt][0], acc[mt][nt][1], acc[mt][nt][2], acc[mt][nt][3],
                             af[mt][0], af[mt][1], af[mt][2], af[mt][3], b0, b1);
            }
        }

        const float* bias = Bp[w];
        float* outp = Op[w];
#pragma unroll
        for (int nt = 0; nt < 4; nt++) {
            int col = wc * 32 + nt * 8 + qln * 2;
            float b0v = 0.f, b1v = 0.f;
            if (bias) { b0v = bias[col]; b1v = bias[col + 1]; }
#pragma unroll
            for (int mt = 0; mt < 2; mt++) {
                int r = row0 + wr * 32 + mt * 16 + qid;
                float o0 = acc[mt][nt][0] + b0v;
                float o1 = acc[mt][nt][1] + b1v;
                float o2 = acc[mt][nt][2] + b0v;
                float o3 = acc[mt][nt][3] + b1v;
                if (act) {
                    o0 = o0 / (1.f + expf(-o0));
                    o1 = o1 / (1.f + expf(-o1));
                    o2 = o2 / (1.f + expf(-o2));
                    o3 = o3 / (1.f + expf(-o3));
                }
                if (r < M)
                    *(float2*)&outp[(size_t)r * DD + col] = make_float2(o0, o1);
                if (r + 8 < M)
                    *(float2*)&outp[(size_t)(r + 8) * DD + col] = make_float2(o2, o3);
            }
        }
    }
}

// ---------------- FUSED: edge GEMM (Ef = edge_attr @ We) + attention scatter ----------------
// Ef never goes to global memory. Per CTA: stage We once, then loop over 64-edge
// tiles: stage edge_attr -> tf32 MMA -> Ef tile in smem -> per-warp attention with
// gathered q/k/v and red.global.add.v4 scatter of UNNORMALIZED messages + denom.
__global__ void __launch_bounds__(256, 2)
fused_edge_kernel(const float* __restrict__ EA, const float* __restrict__ We,
                  const float* __restrict__ Q, const float* __restrict__ K,
                  const float* __restrict__ V, const void* __restrict__ eidx,
                  int E, float* __restrict__ denom, float* __restrict__ AGG) {
    extern __shared__ uint32_t sm[];
    uint32_t* Ws  = sm;                         // [128][WS_STRIDE]
    uint32_t* As  = sm + WS_ELEMS;              // [64][AS_STRIDE], reused as Ef
    int* ssrc = (int*)(sm + WS_ELEMS + AS_ELEMS);
    int* sdst = ssrc + 64;

    int tid = threadIdx.x;
    int wid = tid >> 5;
    int lane = tid & 31;
    int is64 = g_is64;

    // stage We (once per CTA; L2-hot)
#pragma unroll
    for (int it = 0; it < 16; it++) {
        int idx = it * 256 + tid;
        int k = idx >> 5, c4 = idx & 31;
        float4 v = ((const float4*)(We + (size_t)k * DD))[c4];
        uint4 t = make_uint4(f2tf32(v.x), f2tf32(v.y), f2tf32(v.z), f2tf32(v.w));
        *(uint4*)&Ws[k * WS_STRIDE + c4 * 4] = t;
    }

    int wr = wid & 1;
    int wc = wid >> 1;
    int qid = lane >> 2;
    int qln = lane & 3;

    int ntiles = (E + 63) >> 6;
    int t_end = blockIdx.x * TPC + TPC;
    if (t_end > ntiles) t_end = ntiles;

    for (int t = blockIdx.x * TPC; t < t_end; t++) {
        int e0 = t << 6;
        __syncthreads();   // prev Ef consumed; (1st iter: orders Ws staging too)

        // stage edge_attr tile + indices
#pragma unroll
        for (int it = 0; it < 8; it++) {
            int idx = it * 256 + tid;
            int r = idx >> 5, c4 = idx & 31;
            float4 v = make_float4(0.f, 0.f, 0.f, 0.f);
            if (e0 + r < E) v = ((const float4*)(EA + (size_t)(e0 + r) * DD))[c4];
            uint4 tt = make_uint4(f2tf32(v.x), f2tf32(v.y), f2tf32(v.z), f2tf32(v.w));
            *(uint4*)&As[r * AS_STRIDE + c4 * 4] = tt;
        }
        if (tid < 64) {
            long long ee = (long long)(e0 + tid);
            int ok = (e0 + tid) < E;
            ssrc[tid] = ok ? load_idx(eidx, ee, is64) : 0;
            sdst[tid] = ok ? load_idx(eidx, (long long)E + ee, is64) : 0;
        }
        __syncthreads();

        // MMA: Ef_tile[64,128] = A_tile @ We
        float acc[2][4][4];
#pragma unroll
        for (int mt = 0; mt < 2; mt++)
#pragma unroll
            for (int nt = 0; nt < 4; nt++)
#pragma unroll
                for (int j = 0; j < 4; j++) acc[mt][nt][j] = 0.f;

#pragma unroll
        for (int ks = 0; ks < 16; ks++) {
            int k0 = ks * 8;
            uint32_t af[2][4];
#pragma unroll
            for (int mt = 0; mt < 2; mt++) {
                int r = wr * 32 + mt * 16 + qid;
                const uint32_t* ap = &As[r * AS_STRIDE + k0 + qln];
                af[mt][0] = ap[0];
                af[mt][2] = ap[4];
                af[mt][1] = ap[8 * AS_STRIDE];
                af[mt][3] = ap[8 * AS_STRIDE + 4];
            }
#pragma unroll
            for (int nt = 0; nt < 4; nt++) {
                int n0 = wc * 32 + nt * 8;
                uint32_t b0 = Ws[(k0 + qln) * WS_STRIDE + n0 + qid];
                uint32_t b1 = Ws[(k0 + 4 + qln) * WS_STRIDE + n0 + qid];
#pragma unroll
                for (int mt = 0; mt < 2; mt++)
                    mma_tf32(acc[mt][nt][0], acc[mt][nt][1], acc[mt][nt][2], acc[mt][nt][3],
                             af[mt][0], af[mt][1], af[mt][2], af[mt][3], b0, b1);
            }
        }
        __syncthreads();   // all warps done reading As

        // write Ef tile into As buffer (f32)
        float* Es = (float*)As;
#pragma unroll
        for (int nt = 0; nt < 4; nt++) {
            int col = wc * 32 + nt * 8 + qln * 2;
#pragma unroll
            for (int mt = 0; mt < 2; mt++) {
                int r = wr * 32 + mt * 16 + qid;
                *(float2*)&Es[r * AS_STRIDE + col] =
                    make_float2(acc[mt][nt][0], acc[mt][nt][1]);
                *(float2*)&Es[(r + 8) * AS_STRIDE + col] =
                    make_float2(acc[mt][nt][2], acc[mt][nt][3]);
            }
        }
        __syncthreads();

        // attention: warp wid handles edges e0 + wid*8 .. +7
#pragma unroll
        for (int i = 0; i < 8; i++) {
            int le = wid * 8 + i;
            int ee = e0 + le;
            if (ee >= E) break;
            int src = ssrc[le], dst = sdst[le];

            float4 e4 = *(const float4*)&Es[le * AS_STRIDE + lane * 4];
            float4 q4 = *(const float4*)&Q[(size_t)dst * DD + lane * 4];
            float4 k4 = *(const float4*)&K[(size_t)src * DD + lane * 4];

            float p = q4.x * (k4.x + e4.x) + q4.y * (k4.y + e4.y) +
                      q4.z * (k4.z + e4.z) + q4.w * (k4.w + e4.w);
            p += __shfl_xor_sync(0xffffffffu, p, 1);
            p += __shfl_xor_sync(0xffffffffu, p, 2);   // 4 lanes = one head

            float ex = expf(p * 0.25f);
            if ((lane & 3) == 0)
                atomicAdd(&denom[(size_t)dst * 8 + (lane >> 2)], ex);

            float4 v4 = *(const float4*)&V[(size_t)src * DD + lane * 4];
            float m0 = ex * (v4.x + e4.x);
            float m1 = ex * (v4.y + e4.y);
            float m2 = ex * (v4.z + e4.z);
            float m3 = ex * (v4.w + e4.w);

            float* o = &AGG[(size_t)dst * DD + lane * 4];
            asm volatile("red.global.add.v4.f32 [%0], {%1,%2,%3,%4};"
                         :: "l"(o), "f"(m0), "f"(m1), "f"(m2), "f"(m3) : "memory");
        }
    }
}

// ---------------- edge index dtype detection ----------------
__global__ void detect_idx_kernel(const long long* __restrict__ p, int E, int N) {
    if (threadIdx.x == 0 && blockIdx.x == 0) {
        int ok64 = 1;
        int n = (E < 64) ? E : 64;
        for (int i = 0; i < n; i++) {
            long long v = p[i];
            if (v < 0 || v >= (long long)N) { ok64 = 0; break; }
        }
        g_is64 = ok64;
    }
}

// ---------------- zero accumulators ----------------
__global__ void zero_kernel(float* __restrict__ a, size_t na,
                            float* __restrict__ b, size_t nb) {
    size_t i = (size_t)blockIdx.x * blockDim.x + threadIdx.x;
    size_t stride = (size_t)gridDim.x * blockDim.x;
    for (size_t j = i; j < na; j += stride) a[j] = 0.0f;
    for (size_t j = i; j < nb; j += stride) b[j] = 0.0f;
}

// ---------------- h = x + LN(AGG/den + SKIP) ----------------
__global__ void postln1_kernel(const float* __restrict__ x, const float* __restrict__ AGG,
                               const float* __restrict__ SKIP, const float* __restrict__ den,
                               const float* __restrict__ g, const float* __restrict__ b,
                               float* __restrict__ outp, int M) {
    long long gw = ((long long)blockIdx.x * blockDim.x + threadIdx.x) >> 5;
    int lane = threadIdx.x & 31;
    if (gw >= M) return;

    float dh = den[(size_t)gw * 8 + (lane >> 2)];
    float inv = 1.0f / (dh + 1e-16f);

    float4 o = *(const float4*)&AGG[(size_t)gw * DD + lane * 4];
    float4 s = *(const float4*)&SKIP[(size_t)gw * DD + lane * 4];
    o.x = o.x * inv + s.x;
    o.y = o.y * inv + s.y;
    o.z = o.z * inv + s.z;
    o.w = o.w * inv + s.w;

    float sum = o.x + o.y + o.z + o.w;
#pragma unroll
    for (int off = 16; off >= 1; off >>= 1) sum += __shfl_xor_sync(0xffffffffu, sum, off);
    float mu = sum * (1.0f / 128.0f);

    float dx = o.x - mu, dy = o.y - mu, dz = o.z - mu, dw = o.w - mu;
    float ss = dx * dx + dy * dy + dz * dz + dw * dw;
#pragma unroll
    for (int off = 16; off >= 1; off >>= 1) ss += __shfl_xor_sync(0xffffffffu, ss, off);
    float rs = rsqrtf(ss * (1.0f / 128.0f) + 1e-5f);

    float4 gg = *(const float4*)&g[lane * 4];
    float4 bb = *(const float4*)&b[lane * 4];
    float4 xx = *(const float4*)&x[(size_t)gw * DD + lane * 4];

    float4 r;
    r.x = xx.x + dx * rs * gg.x + bb.x;
    r.y = xx.y + dy * rs * gg.y + bb.y;
    r.z = xx.z + dz * rs * gg.z + bb.z;
    r.w = xx.w + dw * rs * gg.w + bb.w;
    *(float4*)&outp[(size_t)gw * DD + lane * 4] = r;
}

// ---------------- out = base + LN(acc) ----------------
__global__ void postln2_kernel(const float* __restrict__ base, const float* __restrict__ acc1,
                               const float* __restrict__ g, const float* __restrict__ b,
                               float* __restrict__ outp, int M) {
    long long gw = ((long long)blockIdx.x * blockDim.x + threadIdx.x) >> 5;
    int lane = threadIdx.x & 31;
    if (gw >= M) return;

    float4 o = *(const float4*)&acc1[(size_t)gw * DD + lane * 4];
    float sum = o.x + o.y + o.z + o.w;
#pragma unroll
    for (int off = 16; off >= 1; off >>= 1) sum += __shfl_xor_sync(0xffffffffu, sum, off);
    float mu = sum * (1.0f / 128.0f);

    float dx = o.x - mu, dy = o.y - mu, dz = o.z - mu, dw = o.w - mu;
    float ss = dx * dx + dy * dy + dz * dz + dw * dw;
#pragma unroll
    for (int off = 16; off >= 1; off >>= 1) ss += __shfl_xor_sync(0xffffffffu, ss, off);
    float rs = rsqrtf(ss * (1.0f / 128.0f) + 1e-5f);

    float4 gg = *(const float4*)&g[lane * 4];
    float4 bb = *(const float4*)&b[lane * 4];
    float4 xx = *(const float4*)&base[(size_t)gw * DD + lane * 4];

    float4 r;
    r.x = xx.x + dx * rs * gg.x + bb.x;
    r.y = xx.y + dy * rs * gg.y + bb.y;
    r.z = xx.z + dz * rs * gg.z + bb.z;
    r.w = xx.w + dw * rs * gg.w + bb.w;
    *(float4*)&outp[(size_t)gw * DD + lane * 4] = r;
}

// ---------------- launch ----------------
extern "C" void kernel_launch(void* const* d_in, const int* in_sizes, int n_in,
                              void* d_out, int out_size) {
    const void*  eidx      = d_in[0];
    const float* x         = (const float*)d_in[1];
    const float* edge_attr = (const float*)d_in[2];
    const float* Wq = (const float*)d_in[3],  *bq = (const float*)d_in[4];
    const float* Wk = (const float*)d_in[5],  *bk = (const float*)d_in[6];
    const float* Wv = (const float*)d_in[7],  *bv = (const float*)d_in[8];
    const float* We = (const float*)d_in[9];
    const float* Wskip = (const float*)d_in[10], *bskip = (const float*)d_in[11];
    const float* W1 = (const float*)d_in[12], *b1 = (const float*)d_in[13];
    const float* W2 = (const float*)d_in[14], *b2 = (const float*)d_in[15];
    const float* g1 = (const float*)d_in[16], *be1 = (const float*)d_in[17];
    const float* g2 = (const float*)d_in[18], *be2 = (const float*)d_in[19];
    float* out = (float*)d_out;

    int N = in_sizes[1] / DD;   // 100000
    int E = in_sizes[2] / DD;   // 600000

    float *pQ, *pK, *pV, *pSK, *pAGG, *pH, *pT1, *pF2, *pDen;
    cudaGetSymbolAddress((void**)&pQ,   g_Q);
    cudaGetSymbolAddress((void**)&pK,   g_K);
    cudaGetSymbolAddress((void**)&pV,   g_V);
    cudaGetSymbolAddress((void**)&pSK,  g_SKIP);
    cudaGetSymbolAddress((void**)&pAGG, g_AGG);
    cudaGetSymbolAddress((void**)&pH,   g_H);
    cudaGetSymbolAddress((void**)&pT1,  g_T1);
    cudaGetSymbolAddress((void**)&pF2,  g_F2);
    cudaGetSymbolAddress((void**)&pDen, g_den);

    cudaFuncSetAttribute(mma_gemm_kernel, cudaFuncAttributeMaxDynamicSharedMemorySize,
                         GEMM_SMEM);
    cudaFuncSetAttribute(fused_edge_kernel, cudaFuncAttributeMaxDynamicSharedMemorySize,
                         FUSED_SMEM);

    // 1. detect edge_index dtype
    detect_idx_kernel<<<1, 32>>>((const long long*)eidx, E, N);

    // 2. zero accumulators
    zero_kernel<<<1024, 256>>>(pDen, (size_t)N * 8, pAGG, (size_t)N * DD);

    // 3. node projections (tensor-core tf32)
    int nb_node = (N + 63) / 64;
    mma_gemm_kernel<<<nb_node, 256, GEMM_SMEM>>>(x, N, 4, 0,
        Wq, Wk, Wv, Wskip, bq, bk, bv, bskip, pQ, pK, pV, pSK);

    // 4. fused edge GEMM + attention (Ef stays in smem)
    int ntiles = (E + 63) / 64;
    int nb_fused = (ntiles + TPC - 1) / TPC;
    fused_edge_kernel<<<nb_fused, 256, FUSED_SMEM>>>(edge_attr, We, pQ, pK, pV,
                                                     eidx, E, pDen, pAGG);

    // 5. h = x + LN(AGG/den + skip)
    int nbw = (N + 7) / 8;
    postln1_kernel<<<nbw, 256>>>(x, pAGG, pSK, pDen, g1, be1, pH, N);

    // 6. FFN
    mma_gemm_kernel<<<nb_node, 256, GEMM_SMEM>>>(pH, N, 1, 1,
        W1, nullptr, nullptr, nullptr, b1, nullptr, nullptr, nullptr,
        pT1, nullptr, nullptr, nullptr);
    mma_gemm_kernel<<<nb_node, 256, GEMM_SMEM>>>(pT1, N, 1, 0,
        W2, nullptr, nullptr, nullptr, b2, nullptr, nullptr, nullptr,
        pF2, nullptr, nullptr, nullptr);

    // 7. out = h + LN(ffn)
    postln2_kernel<<<nbw, 256>>>(pH, pF2, g2, be2, out, N);
}

// round 6
// speedup vs baseline: 2.3386x; 1.0749x over previous
#include <cuda_runtime.h>
#include <cstdint>
#include <cstddef>

// Problem constants
#define NN 100000
#define EE 600000
#define DD 128

// ---------------- scratch ----------------
__device__ float g_Q   [(size_t)NN * DD];
__device__ float g_K   [(size_t)NN * DD];
__device__ float g_V   [(size_t)NN * DD];
__device__ float g_SKIP[(size_t)NN * DD];
__device__ float g_AGG [(size_t)NN * DD];
__device__ float g_H   [(size_t)NN * DD];
__device__ float g_den [(size_t)NN * 8];
__device__ int   g_is64;

// ---------------- tf32 helpers ----------------
__device__ __forceinline__ uint32_t f2tf32(float v) {
    uint32_t r;
    asm("cvt.rna.tf32.f32 %0, %1;" : "=r"(r) : "f"(v));
    return r;
}
__device__ __forceinline__ void mma_tf32(float& d0, float& d1, float& d2, float& d3,
                                         uint32_t a0, uint32_t a1, uint32_t a2, uint32_t a3,
                                         uint32_t b0, uint32_t b1) {
    asm volatile(
        "mma.sync.aligned.m16n8k8.row.col.f32.tf32.tf32.f32 "
        "{%0,%1,%2,%3}, {%4,%5,%6,%7}, {%8,%9}, {%0,%1,%2,%3};"
        : "+f"(d0), "+f"(d1), "+f"(d2), "+f"(d3)
        : "r"(a0), "r"(a1), "r"(a2), "r"(a3), "r"(b0), "r"(b1));
}

#define AS_STRIDE 132
#define WS_STRIDE 136
#define AS_ELEMS  (64 * AS_STRIDE)                 // 8448
#define WS_ELEMS  (128 * WS_STRIDE)                // 17408
#define GEMM_SMEM ((AS_ELEMS + WS_ELEMS) * 4)      // 103424 -> 2 CTAs/SM
#define FUSED_SMEM (GEMM_SMEM + 64 * 2 * 4)

#define TPC 8   // edge tiles per CTA in fused edge kernel

__device__ __forceinline__ int load_idx(const void* p, long long i, int is64) {
    if (is64) return (int)((const long long*)p)[i];
    return ((const int*)p)[i];
}

// ======================================================================
// Shared MMA micro-kernel pieces (macro-free, inlined by hand per use)
// ======================================================================

// ---------------- node projection GEMM (Q,K,V,SKIP share staged x) ----------------
__global__ void __launch_bounds__(256, 2)
mma_gemm_kernel(const float* __restrict__ A, int M, int nw,
                const float* Wg0, const float* Wg1, const float* Wg2, const float* Wg3,
                const float* bg0, const float* bg1, const float* bg2, const float* bg3,
                float* og0, float* og1, float* og2, float* og3) {
    extern __shared__ uint32_t sm[];
    uint32_t* As = sm;
    uint32_t* Ws = sm + AS_ELEMS;

    int tid = threadIdx.x;
    int wid = tid >> 5;
    int lane = tid & 31;
    int row0 = blockIdx.x * 64;

    const float* Wp[4] = {Wg0, Wg1, Wg2, Wg3};
    const float* Bp[4] = {bg0, bg1, bg2, bg3};
    float*       Op[4] = {og0, og1, og2, og3};

#pragma unroll
    for (int it = 0; it < 8; it++) {
        int idx = it * 256 + tid;
        int r = idx >> 5, c4 = idx & 31;
        float4 v = make_float4(0.f, 0.f, 0.f, 0.f);
        if (row0 + r < M) v = ((const float4*)(A + (size_t)(row0 + r) * DD))[c4];
        uint4 t = make_uint4(f2tf32(v.x), f2tf32(v.y), f2tf32(v.z), f2tf32(v.w));
        *(uint4*)&As[r * AS_STRIDE + c4 * 4] = t;
    }

    int wr = wid & 1, wc = wid >> 1;
    int qid = lane >> 2, qln = lane & 3;

    for (int w = 0; w < nw; w++) {
        __syncthreads();
        const float* Wgp = Wp[w];
#pragma unroll
        for (int it = 0; it < 16; it++) {
            int idx = it * 256 + tid;
            int k = idx >> 5, c4 = idx & 31;
            float4 v = ((const float4*)(Wgp + (size_t)k * DD))[c4];
            uint4 t = make_uint4(f2tf32(v.x), f2tf32(v.y), f2tf32(v.z), f2tf32(v.w));
            *(uint4*)&Ws[k * WS_STRIDE + c4 * 4] = t;
        }
        __syncthreads();

        float acc[2][4][4];
#pragma unroll
        for (int mt = 0; mt < 2; mt++)
#pragma unroll
            for (int nt = 0; nt < 4; nt++)
#pragma unroll
                for (int j = 0; j < 4; j++) acc[mt][nt][j] = 0.f;

#pragma unroll
        for (int ks = 0; ks < 16; ks++) {
            int k0 = ks * 8;
            uint32_t af[2][4];
#pragma unroll
            for (int mt = 0; mt < 2; mt++) {
                int r = wr * 32 + mt * 16 + qid;
                const uint32_t* ap = &As[r * AS_STRIDE + k0 + qln];
                af[mt][0] = ap[0];
                af[mt][2] = ap[4];
                af[mt][1] = ap[8 * AS_STRIDE];
                af[mt][3] = ap[8 * AS_STRIDE + 4];
            }
#pragma unroll
            for (int nt = 0; nt < 4; nt++) {
                int n0 = wc * 32 + nt * 8;
                uint32_t b0 = Ws[(k0 + qln) * WS_STRIDE + n0 + qid];
                uint32_t b1 = Ws[(k0 + 4 + qln) * WS_STRIDE + n0 + qid];
#pragma unroll
                for (int mt = 0; mt < 2; mt++)
                    mma_tf32(acc[mt][nt][0], acc[mt][nt][1], acc[mt][nt][2], acc[mt][nt][3],
                             af[mt][0], af[mt][1], af[mt][2], af[mt][3], b0, b1);
            }
        }

        const float* bias = Bp[w];
        float* outp = Op[w];
#pragma unroll
        for (int nt = 0; nt < 4; nt++) {
            int col = wc * 32 + nt * 8 + qln * 2;
            float b0v = bias[col], b1v = bias[col + 1];
#pragma unroll
            for (int mt = 0; mt < 2; mt++) {
                int r = row0 + wr * 32 + mt * 16 + qid;
                if (r < M)
                    *(float2*)&outp[(size_t)r * DD + col] =
                        make_float2(acc[mt][nt][0] + b0v, acc[mt][nt][1] + b1v);
                if (r + 8 < M)
                    *(float2*)&outp[(size_t)(r + 8) * DD + col] =
                        make_float2(acc[mt][nt][2] + b0v, acc[mt][nt][3] + b1v);
            }
        }
    }
}

// ---------------- FUSED: edge GEMM (Ef = edge_attr @ We) + attention scatter ----------------
__global__ void __launch_bounds__(256, 2)
fused_edge_kernel(const float* __restrict__ EA, const float* __restrict__ We,
                  const float* __restrict__ Q, const float* __restrict__ K,
                  const float* __restrict__ V, const void* __restrict__ eidx,
                  int E, float* __restrict__ denom, float* __restrict__ AGG) {
    extern __shared__ uint32_t sm[];
    uint32_t* Ws  = sm;                         // [128][WS_STRIDE]
    uint32_t* As  = sm + WS_ELEMS;              // [64][AS_STRIDE], reused as Ef
    int* ssrc = (int*)(sm + WS_ELEMS + AS_ELEMS);
    int* sdst = ssrc + 64;

    int tid = threadIdx.x;
    int wid = tid >> 5;
    int lane = tid & 31;
    int is64 = g_is64;

    // stage We once
#pragma unroll
    for (int it = 0; it < 16; it++) {
        int idx = it * 256 + tid;
        int k = idx >> 5, c4 = idx & 31;
        float4 v = ((const float4*)(We + (size_t)k * DD))[c4];
        uint4 t = make_uint4(f2tf32(v.x), f2tf32(v.y), f2tf32(v.z), f2tf32(v.w));
        *(uint4*)&Ws[k * WS_STRIDE + c4 * 4] = t;
    }

    int wr = wid & 1, wc = wid >> 1;
    int qid = lane >> 2, qln = lane & 3;

    int ntiles = (E + 63) >> 6;
    int t_end = blockIdx.x * TPC + TPC;
    if (t_end > ntiles) t_end = ntiles;

    for (int t = blockIdx.x * TPC; t < t_end; t++) {
        int e0 = t << 6;
        __syncthreads();

        // stage edge_attr tile + indices
#pragma unroll
        for (int it = 0; it < 8; it++) {
            int idx = it * 256 + tid;
            int r = idx >> 5, c4 = idx & 31;
            float4 v = make_float4(0.f, 0.f, 0.f, 0.f);
            if (e0 + r < E) v = ((const float4*)(EA + (size_t)(e0 + r) * DD))[c4];
            uint4 tt = make_uint4(f2tf32(v.x), f2tf32(v.y), f2tf32(v.z), f2tf32(v.w));
            *(uint4*)&As[r * AS_STRIDE + c4 * 4] = tt;
        }
        if (tid < 64) {
            long long ee = (long long)(e0 + tid);
            int ok = (e0 + tid) < E;
            ssrc[tid] = ok ? load_idx(eidx, ee, is64) : 0;
            sdst[tid] = ok ? load_idx(eidx, (long long)E + ee, is64) : 0;
        }
        __syncthreads();

        // MMA: Ef_tile[64,128] = A_tile @ We
        float acc[2][4][4];
#pragma unroll
        for (int mt = 0; mt < 2; mt++)
#pragma unroll
            for (int nt = 0; nt < 4; nt++)
#pragma unroll
                for (int j = 0; j < 4; j++) acc[mt][nt][j] = 0.f;

#pragma unroll
        for (int ks = 0; ks < 16; ks++) {
            int k0 = ks * 8;
            uint32_t af[2][4];
#pragma unroll
            for (int mt = 0; mt < 2; mt++) {
                int r = wr * 32 + mt * 16 + qid;
                const uint32_t* ap = &As[r * AS_STRIDE + k0 + qln];
                af[mt][0] = ap[0];
                af[mt][2] = ap[4];
                af[mt][1] = ap[8 * AS_STRIDE];
                af[mt][3] = ap[8 * AS_STRIDE + 4];
            }
#pragma unroll
            for (int nt = 0; nt < 4; nt++) {
                int n0 = wc * 32 + nt * 8;
                uint32_t b0 = Ws[(k0 + qln) * WS_STRIDE + n0 + qid];
                uint32_t b1 = Ws[(k0 + 4 + qln) * WS_STRIDE + n0 + qid];
#pragma unroll
                for (int mt = 0; mt < 2; mt++)
                    mma_tf32(acc[mt][nt][0], acc[mt][nt][1], acc[mt][nt][2], acc[mt][nt][3],
                             af[mt][0], af[mt][1], af[mt][2], af[mt][3], b0, b1);
            }
        }
        __syncthreads();

        // Ef tile -> smem (f32, reuse As)
        float* Es = (float*)As;
#pragma unroll
        for (int nt = 0; nt < 4; nt++) {
            int col = wc * 32 + nt * 8 + qln * 2;
#pragma unroll
            for (int mt = 0; mt < 2; mt++) {
                int r = wr * 32 + mt * 16 + qid;
                *(float2*)&Es[r * AS_STRIDE + col] =
                    make_float2(acc[mt][nt][0], acc[mt][nt][1]);
                *(float2*)&Es[(r + 8) * AS_STRIDE + col] =
                    make_float2(acc[mt][nt][2], acc[mt][nt][3]);
            }
        }
        __syncthreads();

        // attention: warp wid handles edges e0 + wid*8 .. +7, FULLY UNROLLED
        // (indices for OOB edges are clamped to 0; atomics predicated)
#pragma unroll
        for (int i = 0; i < 8; i++) {
            int le = wid * 8 + i;
            bool ok = (e0 + le) < E;
            int src = ssrc[le], dst = sdst[le];

            float4 e4 = *(const float4*)&Es[le * AS_STRIDE + lane * 4];
            float4 q4 = *(const float4*)&Q[(size_t)dst * DD + lane * 4];
            float4 k4 = *(const float4*)&K[(size_t)src * DD + lane * 4];
            float4 v4 = *(const float4*)&V[(size_t)src * DD + lane * 4];

            float p = q4.x * (k4.x + e4.x) + q4.y * (k4.y + e4.y) +
                      q4.z * (k4.z + e4.z) + q4.w * (k4.w + e4.w);
            p += __shfl_xor_sync(0xffffffffu, p, 1);
            p += __shfl_xor_sync(0xffffffffu, p, 2);

            float ex = expf(p * 0.25f);
            if (ok) {
                if ((lane & 3) == 0)
                    atomicAdd(&denom[(size_t)dst * 8 + (lane >> 2)], ex);
                float m0 = ex * (v4.x + e4.x);
                float m1 = ex * (v4.y + e4.y);
                float m2 = ex * (v4.z + e4.z);
                float m3 = ex * (v4.w + e4.w);
                float* o = &AGG[(size_t)dst * DD + lane * 4];
                asm volatile("red.global.add.v4.f32 [%0], {%1,%2,%3,%4};"
                             :: "l"(o), "f"(m0), "f"(m1), "f"(m2), "f"(m3) : "memory");
            }
        }
    }
}

// ---------------- FUSED FFN: out = H + LN(silu(H@W1+b1)@W2 + b2) ----------------
__global__ void __launch_bounds__(256, 2)
ffn_kernel(const float* __restrict__ H,
           const float* __restrict__ W1, const float* __restrict__ b1,
           const float* __restrict__ W2, const float* __restrict__ b2,
           const float* __restrict__ g, const float* __restrict__ be,
           float* __restrict__ outp, int M) {
    extern __shared__ uint32_t sm[];
    uint32_t* As = sm;               // H tile, then T1 tile (tf32)
    uint32_t* Ws = sm + AS_ELEMS;    // W1, then W2, then F2 tile (f32)

    int tid = threadIdx.x;
    int wid = tid >> 5;
    int lane = tid & 31;
    int row0 = blockIdx.x * 64;

    // stage H tile (tf32)
#pragma unroll
    for (int it = 0; it < 8; it++) {
        int idx = it * 256 + tid;
        int r = idx >> 5, c4 = idx & 31;
        float4 v = make_float4(0.f, 0.f, 0.f, 0.f);
        if (row0 + r < M) v = ((const float4*)(H + (size_t)(row0 + r) * DD))[c4];
        uint4 t = make_uint4(f2tf32(v.x), f2tf32(v.y), f2tf32(v.z), f2tf32(v.w));
        *(uint4*)&As[r * AS_STRIDE + c4 * 4] = t;
    }
    // stage W1 (tf32)
#pragma unroll
    for (int it = 0; it < 16; it++) {
        int idx = it * 256 + tid;
        int k = idx >> 5, c4 = idx & 31;
        float4 v = ((const float4*)(W1 + (size_t)k * DD))[c4];
        uint4 t = make_uint4(f2tf32(v.x), f2tf32(v.y), f2tf32(v.z), f2tf32(v.w));
        *(uint4*)&Ws[k * WS_STRIDE + c4 * 4] = t;
    }
    __syncthreads();

    int wr = wid & 1, wc = wid >> 1;
    int qid = lane >> 2, qln = lane & 3;

    // ---- MMA 1: T = H @ W1 ----
    float acc[2][4][4];
#pragma unroll
    for (int mt = 0; mt < 2; mt++)
#pragma unroll
        for (int nt = 0; nt < 4; nt++)
#pragma unroll
            for (int j = 0; j < 4; j++) acc[mt][nt][j] = 0.f;

#pragma unroll
    for (int ks = 0; ks < 16; ks++) {
        int k0 = ks * 8;
        uint32_t af[2][4];
#pragma unroll
        for (int mt = 0; mt < 2; mt++) {
            int r = wr * 32 + mt * 16 + qid;
            const uint32_t* ap = &As[r * AS_STRIDE + k0 + qln];
            af[mt][0] = ap[0];
            af[mt][2] = ap[4];
            af[mt][1] = ap[8 * AS_STRIDE];
            af[mt][3] = ap[8 * AS_STRIDE + 4];
        }
#pragma unroll
        for (int nt = 0; nt < 4; nt++) {
            int n0 = wc * 32 + nt * 8;
            uint32_t b0 = Ws[(k0 + qln) * WS_STRIDE + n0 + qid];
            uint32_t b1v = Ws[(k0 + 4 + qln) * WS_STRIDE + n0 + qid];
#pragma unroll
            for (int mt = 0; mt < 2; mt++)
                mma_tf32(acc[mt][nt][0], acc[mt][nt][1], acc[mt][nt][2], acc[mt][nt][3],
                         af[mt][0], af[mt][1], af[mt][2], af[mt][3], b0, b1v);
        }
    }
    __syncthreads();   // done reading As (H) and Ws (W1)

    // T1 = silu(acc + b1) -> As (tf32); stage W2 -> Ws (tf32)
#pragma unroll
    for (int nt = 0; nt < 4; nt++) {
        int col = wc * 32 + nt * 8 + qln * 2;
        float c0 = b1[col], c1 = b1[col + 1];
#pragma unroll
        for (int mt = 0; mt < 2; mt++) {
            int r = wr * 32 + mt * 16 + qid;
            float o0 = acc[mt][nt][0] + c0;
            float o1 = acc[mt][nt][1] + c1;
            float o2 = acc[mt][nt][2] + c0;
            float o3 = acc[mt][nt][3] + c1;
            o0 = o0 / (1.f + expf(-o0));
            o1 = o1 / (1.f + expf(-o1));
            o2 = o2 / (1.f + expf(-o2));
            o3 = o3 / (1.f + expf(-o3));
            As[r * AS_STRIDE + col]       = f2tf32(o0);
            As[r * AS_STRIDE + col + 1]   = f2tf32(o1);
            As[(r + 8) * AS_STRIDE + col]     = f2tf32(o2);
            As[(r + 8) * AS_STRIDE + col + 1] = f2tf32(o3);
        }
    }
#pragma unroll
    for (int it = 0; it < 16; it++) {
        int idx = it * 256 + tid;
        int k = idx >> 5, c4 = idx & 31;
        float4 v = ((const float4*)(W2 + (size_t)k * DD))[c4];
        uint4 t = make_uint4(f2tf32(v.x), f2tf32(v.y), f2tf32(v.z), f2tf32(v.w));
        *(uint4*)&Ws[k * WS_STRIDE + c4 * 4] = t;
    }
    __syncthreads();

    // ---- MMA 2: F = T1 @ W2 ----
#pragma unroll
    for (int mt = 0; mt < 2; mt++)
#pragma unroll
        for (int nt = 0; nt < 4; nt++)
#pragma unroll
            for (int j = 0; j < 4; j++) acc[mt][nt][j] = 0.f;

#pragma unroll
    for (int ks = 0; ks < 16; ks++) {
        int k0 = ks * 8;
        uint32_t af[2][4];
#pragma unroll
        for (int mt = 0; mt < 2; mt++) {
            int r = wr * 32 + mt * 16 + qid;
            const uint32_t* ap = &As[r * AS_STRIDE + k0 + qln];
            af[mt][0] = ap[0];
            af[mt][2] = ap[4];
            af[mt][1] = ap[8 * AS_STRIDE];
            af[mt][3] = ap[8 * AS_STRIDE + 4];
        }
#pragma unroll
        for (int nt = 0; nt < 4; nt++) {
            int n0 = wc * 32 + nt * 8;
            uint32_t b0 = Ws[(k0 + qln) * WS_STRIDE + n0 + qid];
            uint32_t b1v = Ws[(k0 + 4 + qln) * WS_STRIDE + n0 + qid];
#pragma unroll
            for (int mt = 0; mt < 2; mt++)
                mma_tf32(acc[mt][nt][0], acc[mt][nt][1], acc[mt][nt][2], acc[mt][nt][3],
                         af[mt][0], af[mt][1], af[mt][2], af[mt][3], b0, b1v);
        }
    }
    __syncthreads();   // done reading Ws (W2)

    // F2 tile (+b2) -> Ws smem (f32, stride AS_STRIDE)
    float* Es = (float*)Ws;
#pragma unroll
    for (int nt = 0; nt < 4; nt++) {
        int col = wc * 32 + nt * 8 + qln * 2;
        float c0 = b2[col], c1 = b2[col + 1];
#pragma unroll
        for (int mt = 0; mt < 2; mt++) {
            int r = wr * 32 + mt * 16 + qid;
            *(float2*)&Es[r * AS_STRIDE + col] =
                make_float2(acc[mt][nt][0] + c0, acc[mt][nt][1] + c1);
            *(float2*)&Es[(r + 8) * AS_STRIDE + col] =
                make_float2(acc[mt][nt][2] + c0, acc[mt][nt][3] + c1);
        }
    }
    __syncthreads();

    // LN + residual: warp wid handles rows wid*8 .. +7
#pragma unroll
    for (int i = 0; i < 8; i++) {
        int r = wid * 8 + i;
        float4 o = *(float4*)&Es[r * AS_STRIDE + lane * 4];

        float sum = o.x + o.y + o.z + o.w;
#pragma unroll
        for (int off = 16; off >= 1; off >>= 1)
            sum += __shfl_xor_sync(0xffffffffu, sum, off);
        float mu = sum * (1.0f / 128.0f);

        float dx = o.x - mu, dy = o.y - mu, dz = o.z - mu, dw = o.w - mu;
        float ss = dx * dx + dy * dy + dz * dz + dw * dw;
#pragma unroll
        for (int off = 16; off >= 1; off >>= 1)
            ss += __shfl_xor_sync(0xffffffffu, ss, off);
        float rs = rsqrtf(ss * (1.0f / 128.0f) + 1e-5f);

        if (row0 + r < M) {
            float4 gg = *(const float4*)&g[lane * 4];
            float4 bb = *(const float4*)&be[lane * 4];
            float4 hh = *(const float4*)&H[(size_t)(row0 + r) * DD + lane * 4];
            float4 rr;
            rr.x = hh.x + dx * rs * gg.x + bb.x;
            rr.y = hh.y + dy * rs * gg.y + bb.y;
            rr.z = hh.z + dz * rs * gg.z + bb.z;
            rr.w = hh.w + dw * rs * gg.w + bb.w;
            *(float4*)&outp[(size_t)(row0 + r) * DD + lane * 4] = rr;
        }
    }
}

// ---------------- edge index dtype detection ----------------
__global__ void detect_idx_kernel(const long long* __restrict__ p, int E, int N) {
    if (threadIdx.x == 0 && blockIdx.x == 0) {
        int ok64 = 1;
        int n = (E < 64) ? E : 64;
        for (int i = 0; i < n; i++) {
            long long v = p[i];
            if (v < 0 || v >= (long long)N) { ok64 = 0; break; }
        }
        g_is64 = ok64;
    }
}

// ---------------- zero accumulators ----------------
__global__ void zero_kernel(float* __restrict__ a, size_t na,
                            float* __restrict__ b, size_t nb) {
    size_t i = (size_t)blockIdx.x * blockDim.x + threadIdx.x;
    size_t stride = (size_t)gridDim.x * blockDim.x;
    for (size_t j = i; j < na; j += stride) a[j] = 0.0f;
    for (size_t j = i; j < nb; j += stride) b[j] = 0.0f;
}

// ---------------- h = x + LN(AGG/den + SKIP) ----------------
__global__ void postln1_kernel(const float* __restrict__ x, const float* __restrict__ AGG,
                               const float* __restrict__ SKIP, const float* __restrict__ den,
                               const float* __restrict__ g, const float* __restrict__ b,
                               float* __restrict__ outp, int M) {
    long long gw = ((long long)blockIdx.x * blockDim.x + threadIdx.x) >> 5;
    int lane = threadIdx.x & 31;
    if (gw >= M) return;

    float dh = den[(size_t)gw * 8 + (lane >> 2)];
    float inv = 1.0f / (dh + 1e-16f);

    float4 o = *(const float4*)&AGG[(size_t)gw * DD + lane * 4];
    float4 s = *(const float4*)&SKIP[(size_t)gw * DD + lane * 4];
    o.x = o.x * inv + s.x;
    o.y = o.y * inv + s.y;
    o.z = o.z * inv + s.z;
    o.w = o.w * inv + s.w;

    float sum = o.x + o.y + o.z + o.w;
#pragma unroll
    for (int off = 16; off >= 1; off >>= 1) sum += __shfl_xor_sync(0xffffffffu, sum, off);
    float mu = sum * (1.0f / 128.0f);

    float dx = o.x - mu, dy = o.y - mu, dz = o.z - mu, dw = o.w - mu;
    float ss = dx * dx + dy * dy + dz * dz + dw * dw;
#pragma unroll
    for (int off = 16; off >= 1; off >>= 1) ss += __shfl_xor_sync(0xffffffffu, ss, off);
    float rs = rsqrtf(ss * (1.0f / 128.0f) + 1e-5f);

    float4 gg = *(const float4*)&g[lane * 4];
    float4 bb = *(const float4*)&b[lane * 4];
    float4 xx = *(const float4*)&x[(size_t)gw * DD + lane * 4];

    float4 r;
    r.x = xx.x + dx * rs * gg.x + bb.x;
    r.y = xx.y + dy * rs * gg.y + bb.y;
    r.z = xx.z + dz * rs * gg.z + bb.z;
    r.w = xx.w + dw * rs * gg.w + bb.w;
    *(float4*)&outp[(size_t)gw * DD + lane * 4] = r;
}

// ---------------- launch ----------------
extern "C" void kernel_launch(void* const* d_in, const int* in_sizes, int n_in,
                              void* d_out, int out_size) {
    const void*  eidx      = d_in[0];
    const float* x         = (const float*)d_in[1];
    const float* edge_attr = (const float*)d_in[2];
    const float* Wq = (const float*)d_in[3],  *bq = (const float*)d_in[4];
    const float* Wk = (const float*)d_in[5],  *bk = (const float*)d_in[6];
    const float* Wv = (const float*)d_in[7],  *bv = (const float*)d_in[8];
    const float* We = (const float*)d_in[9];
    const float* Wskip = (const float*)d_in[10], *bskip = (const float*)d_in[11];
    const float* W1 = (const float*)d_in[12], *b1 = (const float*)d_in[13];
    const float* W2 = (const float*)d_in[14], *b2 = (const float*)d_in[15];
    const float* g1 = (const float*)d_in[16], *be1 = (const float*)d_in[17];
    const float* g2 = (const float*)d_in[18], *be2 = (const float*)d_in[19];
    float* out = (float*)d_out;

    int N = in_sizes[1] / DD;   // 100000
    int E = in_sizes[2] / DD;   // 600000

    float *pQ, *pK, *pV, *pSK, *pAGG, *pH, *pDen;
    cudaGetSymbolAddress((void**)&pQ,   g_Q);
    cudaGetSymbolAddress((void**)&pK,   g_K);
    cudaGetSymbolAddress((void**)&pV,   g_V);
    cudaGetSymbolAddress((void**)&pSK,  g_SKIP);
    cudaGetSymbolAddress((void**)&pAGG, g_AGG);
    cudaGetSymbolAddress((void**)&pH,   g_H);
    cudaGetSymbolAddress((void**)&pDen, g_den);

    cudaFuncSetAttribute(mma_gemm_kernel, cudaFuncAttributeMaxDynamicSharedMemorySize,
                         GEMM_SMEM);
    cudaFuncSetAttribute(fused_edge_kernel, cudaFuncAttributeMaxDynamicSharedMemorySize,
                         FUSED_SMEM);
    cudaFuncSetAttribute(ffn_kernel, cudaFuncAttributeMaxDynamicSharedMemorySize,
                         GEMM_SMEM);

    detect_idx_kernel<<<1, 32>>>((const long long*)eidx, E, N);
    zero_kernel<<<1024, 256>>>(pDen, (size_t)N * 8, pAGG, (size_t)N * DD);

    // node projections
    int nb_node = (N + 63) / 64;
    mma_gemm_kernel<<<nb_node, 256, GEMM_SMEM>>>(x, N, 4,
        Wq, Wk, Wv, Wskip, bq, bk, bv, bskip, pQ, pK, pV, pSK);

    // fused edge GEMM + attention
    int ntiles = (E + 63) / 64;
    int nb_fused = (ntiles + TPC - 1) / TPC;
    fused_edge_kernel<<<nb_fused, 256, FUSED_SMEM>>>(edge_attr, We, pQ, pK, pV,
                                                     eidx, E, pDen, pAGG);

    // h = x + LN(AGG/den + skip)
    int nbw = (N + 7) / 8;
    postln1_kernel<<<nbw, 256>>>(x, pAGG, pSK, pDen, g1, be1, pH, N);

    // fused FFN + final LN + residual -> out
    ffn_kernel<<<nb_node, 256, GEMM_SMEM>>>(pH, W1, b1, W2, b2, g2, be2, out, N);
}